// round 7
// baseline (speedup 1.0000x reference)
#include <cuda_runtime.h>
#include <math.h>

// ---------------- problem constants ----------------
#define BB   8
#define NN   2048
#define HH   12
#define DD   768
#define DH   64
#define MF   256
#define TT   16384            // B*N tokens
#define RR   196608           // B*H*N head-rows
#define NBH  96               // B*H

// ---------------- scratch (device globals, allowed) ----------------
__device__ float g_q[RR * DH];
__device__ float g_k[RR * DH];
__device__ float g_v[RR * DH];
__device__ float g_qp[RR * MF];          // xp_q then phi_q  (50.3M floats)
__device__ float g_kp[RR * MF];          // xp_k then phi_k
__device__ float g_diag[2 * RR];         // [0]=q, [1]=k
__device__ float g_rmax[2 * RR];         // per-row max of raw xp
__device__ float g_kmax[NBH];            // per-head max for k
__device__ float g_ksum[NBH * MF];
__device__ float g_ctx[NBH * MF * DH];
__device__ float g_dinv[RR];
__device__ float g_attn[TT * DD];        // attention output, token layout

// =====================================================================
// Kernel 1: fused QKV projection. C = x @ W^T + b, written in head layout.
// 128x128 tile, BK=16, 256 threads, 8x8 per thread.
// grid: (768/128=6, 16384/128=128, 3)
// =====================================================================
__global__ __launch_bounds__(256) void gemm_qkv_kernel(
    const float* __restrict__ x,
    const float* __restrict__ Wq, const float* __restrict__ bq,
    const float* __restrict__ Wk, const float* __restrict__ bk,
    const float* __restrict__ Wv, const float* __restrict__ bv)
{
    const int K = DD;
    int z = blockIdx.z;
    const float* W  = (z == 0) ? Wq : (z == 1) ? Wk : Wv;
    const float* bs = (z == 0) ? bq : (z == 1) ? bk : bv;
    float* out      = (z == 0) ? g_q : (z == 1) ? g_k : g_v;

    __shared__ float As[16][132];   // [k][m], 132 = 16B-aligned pad
    __shared__ float Bs[16][132];   // [k][n]

    int tid  = threadIdx.x;
    int row0 = blockIdx.y * 128;
    int col0 = blockIdx.x * 128;
    int lr = tid >> 2;              // 0..63
    int lk = (tid & 3) << 2;        // 0,4,8,12
    int ty = tid >> 4;              // 0..15
    int tx = tid & 15;

    float acc[8][8];
#pragma unroll
    for (int i = 0; i < 8; i++)
#pragma unroll
        for (int j = 0; j < 8; j++) acc[i][j] = 0.f;

    for (int kt = 0; kt < K; kt += 16) {
#pragma unroll
        for (int l = 0; l < 2; l++) {
            int rr = lr + l * 64;
            float4 fa = *(const float4*)(x + (size_t)(row0 + rr) * K + kt + lk);
            As[lk + 0][rr] = fa.x; As[lk + 1][rr] = fa.y;
            As[lk + 2][rr] = fa.z; As[lk + 3][rr] = fa.w;
            float4 fb = *(const float4*)(W + (size_t)(col0 + rr) * K + kt + lk);
            Bs[lk + 0][rr] = fb.x; Bs[lk + 1][rr] = fb.y;
            Bs[lk + 2][rr] = fb.z; Bs[lk + 3][rr] = fb.w;
        }
        __syncthreads();
#pragma unroll
        for (int kk = 0; kk < 16; kk++) {
            float a[8], b[8];
            *(float4*)(a)     = *(const float4*)&As[kk][ty * 8];
            *(float4*)(a + 4) = *(const float4*)&As[kk][ty * 8 + 4];
            *(float4*)(b)     = *(const float4*)&Bs[kk][tx * 8];
            *(float4*)(b + 4) = *(const float4*)&Bs[kk][tx * 8 + 4];
#pragma unroll
            for (int i = 0; i < 8; i++)
#pragma unroll
                for (int j = 0; j < 8; j++) acc[i][j] += a[i] * b[j];
        }
        __syncthreads();
    }

    int c0  = col0 + tx * 8;
    int h   = c0 >> 6;
    int dd0 = c0 & 63;
#pragma unroll
    for (int i = 0; i < 8; i++) {
        int t  = row0 + ty * 8 + i;
        int bT = t >> 11, n = t & 2047;
        size_t base = (((size_t)(bT * HH + h)) * NN + n) * DH + dd0;
        float4 o0 = make_float4(acc[i][0] + bs[c0 + 0], acc[i][1] + bs[c0 + 1],
                                acc[i][2] + bs[c0 + 2], acc[i][3] + bs[c0 + 3]);
        float4 o1 = make_float4(acc[i][4] + bs[c0 + 4], acc[i][5] + bs[c0 + 5],
                                acc[i][6] + bs[c0 + 6], acc[i][7] + bs[c0 + 7]);
        *(float4*)(out + base)     = o0;
        *(float4*)(out + base + 4) = o1;
    }
}

// =====================================================================
// Kernel 2: diag[r] = 0.0625 * sum(row^2), warp per row.
// grid: (RR/8, 2)  block 256
// =====================================================================
__global__ void diag_kernel()
{
    int z = blockIdx.y;
    const float* inp = z ? g_k : g_q;
    int warp = threadIdx.x >> 5, lane = threadIdx.x & 31;
    int r = blockIdx.x * 8 + warp;
    const float* p = inp + (size_t)r * DH;
    float a = p[lane], b = p[lane + 32];
    float s = a * a + b * b;
#pragma unroll
    for (int o = 16; o; o >>= 1) s += __shfl_xor_sync(0xffffffffu, s, o);
    if (lane == 0) g_diag[z * RR + r] = s * 0.0625f;
}

// =====================================================================
// Kernel 3: raw xp = data_normalizer * (inp @ proj^T)   [RR x 256]
// 64x64 tile, BK=16, K=64. grid: (256/64=4, RR/64=3072, 2)
// =====================================================================
__global__ __launch_bounds__(256) void feat_kernel(const float* __restrict__ proj)
{
    int z = blockIdx.z;
    const float* inp = z ? g_k : g_q;
    float* outp      = z ? g_kp : g_qp;
    int r0 = blockIdx.y * 64;
    int m0 = blockIdx.x * 64;

    __shared__ float As[16][68];   // [k][row]
    __shared__ float Bs[16][68];   // [k][m]

    int tid = threadIdx.x;
    int lr = tid >> 2;
    int lk = (tid & 3) << 2;
    int ty = tid >> 4, tx = tid & 15;

    float acc[4][4];
#pragma unroll
    for (int i = 0; i < 4; i++)
#pragma unroll
        for (int j = 0; j < 4; j++) acc[i][j] = 0.f;

    for (int kt = 0; kt < DH; kt += 16) {
        float4 fa = *(const float4*)(inp + (size_t)(r0 + lr) * DH + kt + lk);
        As[lk + 0][lr] = fa.x; As[lk + 1][lr] = fa.y;
        As[lk + 2][lr] = fa.z; As[lk + 3][lr] = fa.w;
        float4 fb = *(const float4*)(proj + (size_t)(m0 + lr) * DH + kt + lk);
        Bs[lk + 0][lr] = fb.x; Bs[lk + 1][lr] = fb.y;
        Bs[lk + 2][lr] = fb.z; Bs[lk + 3][lr] = fb.w;
        __syncthreads();
#pragma unroll
        for (int kk = 0; kk < 16; kk++) {
            float a[4], b[4];
            *(float4*)a = *(const float4*)&As[kk][ty * 4];
            *(float4*)b = *(const float4*)&Bs[kk][tx * 4];
#pragma unroll
            for (int i = 0; i < 4; i++)
#pragma unroll
                for (int j = 0; j < 4; j++) acc[i][j] += a[i] * b[j];
        }
        __syncthreads();
    }

    const float dn = 0.35355339059327373f;   // 64^-0.25
#pragma unroll
    for (int i = 0; i < 4; i++) {
        int r = r0 + ty * 4 + i;
        float4 o = make_float4(acc[i][0] * dn, acc[i][1] * dn,
                               acc[i][2] * dn, acc[i][3] * dn);
        *(float4*)(outp + (size_t)r * MF + m0 + tx * 4) = o;
    }
}

// =====================================================================
// Kernel 4: per-row max of raw xp, warp per row. grid (RR/8, 2)
// =====================================================================
__global__ void rowmax_kernel()
{
    int z = blockIdx.y;
    const float* xp = z ? g_kp : g_qp;
    int warp = threadIdx.x >> 5, lane = threadIdx.x & 31;
    int r = blockIdx.x * 8 + warp;
    const float* p = xp + (size_t)r * MF;
    float mx = -1e30f;
#pragma unroll
    for (int i = 0; i < 8; i++) mx = fmaxf(mx, p[lane + i * 32]);
#pragma unroll
    for (int o = 16; o; o >>= 1) mx = fmaxf(mx, __shfl_xor_sync(0xffffffffu, mx, o));
    if (lane == 0) g_rmax[z * RR + r] = mx;
}

// =====================================================================
// Kernel 5: per-head max over k rows + zero ksum. grid (96), block 256
// =====================================================================
__global__ void kheadmax_kernel()
{
    int bh = blockIdx.x, tid = threadIdx.x;
    const float* p = g_rmax + RR + (size_t)bh * NN;
    float mx = -1e30f;
    for (int i = tid; i < NN; i += 256) mx = fmaxf(mx, p[i]);
    __shared__ float sm[256];
    sm[tid] = mx;
    __syncthreads();
    for (int s = 128; s > 0; s >>= 1) {
        if (tid < s) sm[tid] = fmaxf(sm[tid], sm[tid + s]);
        __syncthreads();
    }
    if (tid == 0) g_kmax[bh] = sm[0];
    g_ksum[bh * MF + tid] = 0.f;
}

// =====================================================================
// Kernel 6: phi = ratio*(exp(xp - diag - m) + eps), in place.
// Column-parallel (coalesced). k path also accumulates ksum.
// grid (NN/256=8, 96, 2), block 256
// =====================================================================
__global__ void expphi_kernel()
{
    int isK = blockIdx.z;
    int bh  = blockIdx.y;
    int m   = threadIdx.x;
    int r0  = bh * NN + blockIdx.x * 256;
    float* buf = isK ? g_kp : g_qp;
    float headsub = isK ? g_kmax[bh] : 0.f;
    const float* diag = g_diag + (isK ? RR : 0);
    float acc = 0.f;
    for (int i = 0; i < 256; i++) {
        int r = r0 + i;
        float mv = isK ? headsub : g_rmax[r];          // q-part of g_rmax at offset 0
        size_t idx = (size_t)r * MF + m;
        float ph = 0.0625f * (expf(buf[idx] - diag[r] - mv) + 1e-4f);
        buf[idx] = ph;
        acc += ph;
    }
    if (isK) atomicAdd(&g_ksum[bh * MF + m], acc);
}

// =====================================================================
// Kernel 7: ctx[bh][m][d] = sum_n kp[bh][n][m] * v[bh][n][d]  (TN GEMM)
// 64(m) x 64(d) tile, BK=16 over n. grid (256/64=4, 96), block 256
// =====================================================================
__global__ __launch_bounds__(256) void ctx_kernel()
{
    int bh = blockIdx.y;
    int m0 = blockIdx.x * 64;
    const float* kp = g_kp + (size_t)bh * NN * MF;
    const float* v  = g_v  + (size_t)bh * NN * DH;

    __shared__ float Ks[16][64];
    __shared__ float Vs[16][64];

    int tid = threadIdx.x;
    int kn  = tid >> 4;
    int c4  = (tid & 15) << 2;
    int ty  = tid >> 4, tx = tid & 15;

    float acc[4][4];
#pragma unroll
    for (int i = 0; i < 4; i++)
#pragma unroll
        for (int j = 0; j < 4; j++) acc[i][j] = 0.f;

    for (int n0 = 0; n0 < NN; n0 += 16) {
        *(float4*)&Ks[kn][c4] = *(const float4*)(kp + (size_t)(n0 + kn) * MF + m0 + c4);
        *(float4*)&Vs[kn][c4] = *(const float4*)(v  + (size_t)(n0 + kn) * DH + c4);
        __syncthreads();
#pragma unroll
        for (int k = 0; k < 16; k++) {
            float a[4], b[4];
            *(float4*)a = *(const float4*)&Ks[k][ty * 4];
            *(float4*)b = *(const float4*)&Vs[k][tx * 4];
#pragma unroll
            for (int i = 0; i < 4; i++)
#pragma unroll
                for (int j = 0; j < 4; j++) acc[i][j] += a[i] * b[j];
        }
        __syncthreads();
    }
#pragma unroll
    for (int i = 0; i < 4; i++) {
        float4 o = make_float4(acc[i][0], acc[i][1], acc[i][2], acc[i][3]);
        *(float4*)(g_ctx + ((size_t)bh * MF + m0 + ty * 4 + i) * DH + tx * 4) = o;
    }
}

// =====================================================================
// Kernel 8: dinv[r] = 1 / sum_m qp[r][m]*ksum[bh][m], warp per row.
// grid (RR/8), block 256
// =====================================================================
__global__ void dden_kernel()
{
    int warp = threadIdx.x >> 5, lane = threadIdx.x & 31;
    int r  = blockIdx.x * 8 + warp;
    int bh = r >> 11;
    const float* qp = g_qp + (size_t)r * MF;
    const float* ks = g_ksum + bh * MF;
    float s = 0.f;
#pragma unroll
    for (int i = 0; i < 8; i++) s += qp[lane + i * 32] * ks[lane + i * 32];
#pragma unroll
    for (int o = 16; o; o >>= 1) s += __shfl_xor_sync(0xffffffffu, s, o);
    if (lane == 0) g_dinv[r] = 1.f / s;
}

// =====================================================================
// Kernel 9: out_attn[r][d] = dinv[r] * sum_m qp[r][m] * ctx[bh][m][d]
// 64(rows) x 64(d) tile, BK=16 over m. grid (RR/64=3072), block 256.
// Writes into token layout g_attn[t][h*64+d].
// =====================================================================
__global__ __launch_bounds__(256) void outattn_kernel()
{
    int r0 = blockIdx.x * 64;
    int bh = r0 >> 11;                 // constant within the block (64 | 2048)
    const float* cx = g_ctx + (size_t)bh * MF * DH;

    __shared__ float As[16][68];       // [mk][row]
    __shared__ float Bs[16][64];       // [mk][d]

    int tid = threadIdx.x;
    int lr = tid >> 2;
    int lk = (tid & 3) << 2;
    int kn = tid >> 4;
    int c4 = (tid & 15) << 2;
    int ty = tid >> 4, tx = tid & 15;

    float acc[4][4];
#pragma unroll
    for (int i = 0; i < 4; i++)
#pragma unroll
        for (int j = 0; j < 4; j++) acc[i][j] = 0.f;

    for (int m0 = 0; m0 < MF; m0 += 16) {
        float4 fa = *(const float4*)(g_qp + (size_t)(r0 + lr) * MF + m0 + lk);
        As[lk + 0][lr] = fa.x; As[lk + 1][lr] = fa.y;
        As[lk + 2][lr] = fa.z; As[lk + 3][lr] = fa.w;
        *(float4*)&Bs[kn][c4] = *(const float4*)(cx + (size_t)(m0 + kn) * DH + c4);
        __syncthreads();
#pragma unroll
        for (int k = 0; k < 16; k++) {
            float a[4], b[4];
            *(float4*)a = *(const float4*)&As[k][ty * 4];
            *(float4*)b = *(const float4*)&Bs[k][tx * 4];
#pragma unroll
            for (int i = 0; i < 4; i++)
#pragma unroll
                for (int j = 0; j < 4; j++) acc[i][j] += a[i] * b[j];
        }
        __syncthreads();
    }

    int b = bh / HH;
    int h = bh - b * HH;
#pragma unroll
    for (int i = 0; i < 4; i++) {
        int r = r0 + ty * 4 + i;
        float di = g_dinv[r];
        int n = r & 2047;
        int t = b * NN + n;
        float4 o = make_float4(acc[i][0] * di, acc[i][1] * di,
                               acc[i][2] * di, acc[i][3] * di);
        *(float4*)(g_attn + (size_t)t * DD + h * DH + tx * 4) = o;
    }
}

// =====================================================================
// Kernel 10: final projection: out = attn @ Wo^T + bo. Same 128x128 SGEMM.
// grid (6, 128), block 256
// =====================================================================
__global__ __launch_bounds__(256) void gemm_out_kernel(
    const float* __restrict__ Wo, const float* __restrict__ bo,
    float* __restrict__ out)
{
    const int K = DD;
    __shared__ float As[16][132];
    __shared__ float Bs[16][132];

    int tid  = threadIdx.x;
    int row0 = blockIdx.y * 128;
    int col0 = blockIdx.x * 128;
    int lr = tid >> 2;
    int lk = (tid & 3) << 2;
    int ty = tid >> 4;
    int tx = tid & 15;

    float acc[8][8];
#pragma unroll
    for (int i = 0; i < 8; i++)
#pragma unroll
        for (int j = 0; j < 8; j++) acc[i][j] = 0.f;

    for (int kt = 0; kt < K; kt += 16) {
#pragma unroll
        for (int l = 0; l < 2; l++) {
            int rr = lr + l * 64;
            float4 fa = *(const float4*)(g_attn + (size_t)(row0 + rr) * K + kt + lk);
            As[lk + 0][rr] = fa.x; As[lk + 1][rr] = fa.y;
            As[lk + 2][rr] = fa.z; As[lk + 3][rr] = fa.w;
            float4 fb = *(const float4*)(Wo + (size_t)(col0 + rr) * K + kt + lk);
            Bs[lk + 0][rr] = fb.x; Bs[lk + 1][rr] = fb.y;
            Bs[lk + 2][rr] = fb.z; Bs[lk + 3][rr] = fb.w;
        }
        __syncthreads();
#pragma unroll
        for (int kk = 0; kk < 16; kk++) {
            float a[8], b[8];
            *(float4*)(a)     = *(const float4*)&As[kk][ty * 8];
            *(float4*)(a + 4) = *(const float4*)&As[kk][ty * 8 + 4];
            *(float4*)(b)     = *(const float4*)&Bs[kk][tx * 8];
            *(float4*)(b + 4) = *(const float4*)&Bs[kk][tx * 8 + 4];
#pragma unroll
            for (int i = 0; i < 8; i++)
#pragma unroll
                for (int j = 0; j < 8; j++) acc[i][j] += a[i] * b[j];
        }
        __syncthreads();
    }

    int c0 = col0 + tx * 8;
#pragma unroll
    for (int i = 0; i < 8; i++) {
        int t = row0 + ty * 8 + i;
        float4 o0 = make_float4(acc[i][0] + bo[c0 + 0], acc[i][1] + bo[c0 + 1],
                                acc[i][2] + bo[c0 + 2], acc[i][3] + bo[c0 + 3]);
        float4 o1 = make_float4(acc[i][4] + bo[c0 + 4], acc[i][5] + bo[c0 + 5],
                                acc[i][6] + bo[c0 + 6], acc[i][7] + bo[c0 + 7]);
        *(float4*)(out + (size_t)t * DD + c0)     = o0;
        *(float4*)(out + (size_t)t * DD + c0 + 4) = o1;
    }
}

// =====================================================================
extern "C" void kernel_launch(void* const* d_in, const int* in_sizes, int n_in,
                              void* d_out, int out_size)
{
    const float* x    = (const float*)d_in[0];
    const float* Wq   = (const float*)d_in[1];
    const float* bq   = (const float*)d_in[2];
    const float* Wk   = (const float*)d_in[3];
    const float* bk   = (const float*)d_in[4];
    const float* Wv   = (const float*)d_in[5];
    const float* bv   = (const float*)d_in[6];
    const float* Wo   = (const float*)d_in[7];
    const float* bo   = (const float*)d_in[8];
    const float* proj = (const float*)d_in[9];
    float* out = (float*)d_out;

    gemm_qkv_kernel<<<dim3(DD / 128, TT / 128, 3), 256>>>(x, Wq, bq, Wk, bk, Wv, bv);
    diag_kernel<<<dim3(RR / 8, 2), 256>>>();
    feat_kernel<<<dim3(MF / 64, RR / 64, 2), 256>>>(proj);
    rowmax_kernel<<<dim3(RR / 8, 2), 256>>>();
    kheadmax_kernel<<<NBH, 256>>>();
    expphi_kernel<<<dim3(NN / 256, NBH, 2), 256>>>();
    ctx_kernel<<<dim3(MF / 64, NBH), 256>>>();
    dden_kernel<<<RR / 8, 256>>>();
    outattn_kernel<<<RR / 64, 256>>>();
    gemm_out_kernel<<<dim3(DD / 128, TT / 128), 256>>>(Wo, bo, out);
}

// round 13
// speedup vs baseline: 1.3816x; 1.3816x over previous
#include <cuda_runtime.h>
#include <cuda_bf16.h>
#include <math.h>
#include <stdint.h>

// ---------------- problem constants ----------------
#define BB   8
#define NN   2048
#define HH   12
#define DD   768
#define DH   64
#define MF   256
#define TT   16384            // B*N tokens
#define RR   196608           // B*H*N head-rows
#define NBH  96               // B*H

// ---------------- fp32 scratch ----------------
__device__ float g_q[RR * DH];
__device__ float g_k[RR * DH];
__device__ float g_v[RR * DH];
__device__ float g_qp[RR * MF];
__device__ float g_kp[RR * MF];
__device__ float g_diag[2 * RR];
__device__ float g_rmax[2 * RR];
__device__ float g_kmax[NBH];
__device__ float g_ksum[NBH * MF];
__device__ float g_ctx[NBH * MF * DH];
__device__ float g_dinv[RR];
__device__ float g_attn[TT * DD];
__device__ float g_bqkv[3 * DD];

// ---------------- bf16 split scratch ----------------
__device__ __nv_bfloat16 g_xhi[TT * DD],  g_xlo[TT * DD];
__device__ __nv_bfloat16 g_wqkv_hi[3 * DD * DD], g_wqkv_lo[3 * DD * DD];
__device__ __nv_bfloat16 g_wo_hi[DD * DD], g_wo_lo[DD * DD];
__device__ __nv_bfloat16 g_proj_hi[MF * DH], g_proj_lo[MF * DH];
__device__ __nv_bfloat16 g_qhi[RR * DH], g_qlo[RR * DH];
__device__ __nv_bfloat16 g_khi[RR * DH], g_klo[RR * DH];
__device__ __nv_bfloat16 g_ahi[TT * DD], g_alo[TT * DD];

// =====================================================================
// helpers (base-ISA only: ldmatrix / mma.sync / cp.async)
// =====================================================================
__device__ __forceinline__ uint32_t smem_u32(const void* p) {
    uint32_t a;
    asm("{ .reg .u64 t; cvta.to.shared.u64 t, %1; cvt.u32.u64 %0, t; }" : "=r"(a) : "l"(p));
    return a;
}

#define LDSM4(r, addr) \
    asm volatile("ldmatrix.sync.aligned.m8n8.x4.shared.b16 {%0,%1,%2,%3}, [%4];" \
        : "=r"((r)[0]), "=r"((r)[1]), "=r"((r)[2]), "=r"((r)[3]) : "r"(addr))

#define MMA16816(c, a, b0, b1) \
    asm volatile("mma.sync.aligned.m16n8k16.row.col.f32.bf16.bf16.f32 " \
        "{%0,%1,%2,%3}, {%4,%5,%6,%7}, {%8,%9}, {%0,%1,%2,%3};" \
        : "+f"((c)[0]), "+f"((c)[1]), "+f"((c)[2]), "+f"((c)[3]) \
        : "r"((a)[0]), "r"((a)[1]), "r"((a)[2]), "r"((a)[3]), "r"(b0), "r"(b1))

#define CP_ASYNC16(saddr, gptr) \
    asm volatile("cp.async.cg.shared.global [%0], [%1], 16;" :: "r"(saddr), "l"(gptr))
#define CP_COMMIT() asm volatile("cp.async.commit_group;" ::: "memory")

// =====================================================================
// per-MODE epilogue store of a (v0, v1) pair at logical (t, c)
// =====================================================================
template<int MODE, int ISK>
__device__ __forceinline__ void store_pair(int t, int c, float v0, float v1,
                                           const float* __restrict__ bias,
                                           float* __restrict__ outp)
{
    if (MODE == 0) {
        int seg = c / DD; int oc = c - seg * DD;
        int h = oc >> 6, d0 = oc & 63;
        float* op = (seg == 0) ? g_q : (seg == 1) ? g_k : g_v;
        int bT = t >> 11, n = t & 2047;
        float2 o = make_float2(v0 + g_bqkv[c], v1 + g_bqkv[c + 1]);
        *(float2*)(op + (((size_t)(bT * HH + h)) * NN + n) * DH + d0) = o;
    } else if (MODE == 1) {
        *(float2*)(outp + (size_t)t * DD + c) =
            make_float2(v0 + bias[c], v1 + bias[c + 1]);
    } else {
        const float dnv = 0.35355339059327373f;   // 64^-0.25
        float* dst = ISK ? g_kp : g_qp;
        *(float2*)(dst + (size_t)t * MF + c) = make_float2(v0 * dnv, v1 * dnv);
    }
}

// =====================================================================
// split-fp32 HMMA GEMM: C[M x N] = (Ahi+Alo) @ (Bhi+Blo)^T
// K concat = 3*KD segments: [Ahi|Alo|Ahi] x [Bhi|Bhi|Blo]
// 128x128 CTA tile, BK=32, 8 warps (4m x 2n), warp tile 32x64.
// SMEM rows padded to 40 bf16 (80B stride, 16B-aligned). cp.async
// double-buffered; each thread copies its full 32B half via 2x16B.
// MODE 0: QKV -> g_q/g_k/g_v head layout (+g_bqkv)
// MODE 1: out-proj -> outp (+bias)
// MODE 2: feat (q/k by ISK) -> g_qp/g_kp * dn
// =====================================================================
template<int MODE, int ISK, int KD>
__global__ __launch_bounds__(256) void mma_gemm(const float* __restrict__ bias,
                                                float* __restrict__ outp)
{
    __shared__ __nv_bfloat16 shA[2 * 128 * 40];
    __shared__ __nv_bfloat16 shB[2 * 128 * 40];

    const int tid  = threadIdx.x;
    const int lane = tid & 31;
    const int wid  = tid >> 5;
    const int wm   = wid & 3;        // 0..3  -> 32-row slice
    const int wn   = wid >> 2;       // 0..1  -> 64-col slice
    const int row0 = blockIdx.y * 128;
    const int col0 = blockIdx.x * 128;

    const __nv_bfloat16 *Ahi, *Alo, *Bhi, *Blo;
    if (MODE == 0)      { Ahi = g_xhi; Alo = g_xlo; Bhi = g_wqkv_hi; Blo = g_wqkv_lo; }
    else if (MODE == 1) { Ahi = g_ahi; Alo = g_alo; Bhi = g_wo_hi;   Blo = g_wo_lo;   }
    else                { Ahi = ISK ? g_khi : g_qhi; Alo = ISK ? g_klo : g_qlo;
                          Bhi = g_proj_hi; Blo = g_proj_lo; }

    const uint32_t smA = smem_u32(shA);
    const uint32_t smB = smem_u32(shB);

    const int rowL  = tid >> 1;          // 0..127
    const int halfE = (tid & 1) * 16;    // element offset of 16-bf16 half

    const int numT = 3 * KD / 32;

    // Each tile: 128 rows x 32 bf16 = 8KB/operand. Each thread copies 16
    // contiguous bf16 (32B) per operand = 2 x 16B cp.async.
#define LOAD_TILE(I, BUF) do {                                                   \
        int kcat = (I) * 32; int seg = kcat / KD; int koff = kcat - seg * KD;    \
        const __nv_bfloat16* Ap = (seg == 1) ? Alo : Ahi;                        \
        const __nv_bfloat16* Bp = (seg == 2) ? Blo : Bhi;                        \
        const __nv_bfloat16* ag = Ap + (size_t)(row0 + rowL) * KD + koff + halfE; \
        const __nv_bfloat16* bg = Bp + (size_t)(col0 + rowL) * KD + koff + halfE; \
        uint32_t sa  = smA + ((BUF) * 128 * 40 + rowL * 40 + halfE) * 2;         \
        uint32_t sbv = smB + ((BUF) * 128 * 40 + rowL * 40 + halfE) * 2;         \
        CP_ASYNC16(sa,       ag);                                                \
        CP_ASYNC16(sa  + 16, ag + 8);                                            \
        CP_ASYNC16(sbv,      bg);                                                \
        CP_ASYNC16(sbv + 16, bg + 8);                                            \
    } while (0)

    float c[2][8][4];
#pragma unroll
    for (int mf = 0; mf < 2; mf++)
#pragma unroll
        for (int nf = 0; nf < 8; nf++)
#pragma unroll
            for (int j = 0; j < 4; j++) c[mf][nf][j] = 0.f;

    LOAD_TILE(0, 0);
    CP_COMMIT();

    const int lrow = lane & 15;
    const int lcol = (lane >> 4) << 3;

    for (int i = 0; i < numT; i++) {
        if (i + 1 < numT) {
            LOAD_TILE(i + 1, (i + 1) & 1);
            CP_COMMIT();
            asm volatile("cp.async.wait_group 1;" ::: "memory");
        } else {
            asm volatile("cp.async.wait_group 0;" ::: "memory");
        }
        __syncthreads();

        const int buf = i & 1;
        const uint32_t baseA = smA + buf * (128 * 40 * 2);
        const uint32_t baseB = smB + buf * (128 * 40 * 2);

#pragma unroll
        for (int k16 = 0; k16 < 32; k16 += 16) {
            uint32_t a[2][4], bq[4][4];
#pragma unroll
            for (int mf = 0; mf < 2; mf++) {
                uint32_t ad = baseA + ((wm * 32 + mf * 16 + lrow) * 40 + k16 + lcol) * 2;
                LDSM4(a[mf], ad);
            }
#pragma unroll
            for (int nf4 = 0; nf4 < 4; nf4++) {
                uint32_t bd = baseB + ((wn * 64 + nf4 * 16 + lrow) * 40 + k16 + lcol) * 2;
                LDSM4(bq[nf4], bd);
            }
#pragma unroll
            for (int mf = 0; mf < 2; mf++)
#pragma unroll
                for (int nf4 = 0; nf4 < 4; nf4++) {
                    MMA16816(c[mf][nf4 * 2],     a[mf], bq[nf4][0], bq[nf4][2]);
                    MMA16816(c[mf][nf4 * 2 + 1], a[mf], bq[nf4][1], bq[nf4][3]);
                }
        }
        __syncthreads();
    }
#undef LOAD_TILE

    // epilogue: C frag m16n8 -> (row = lane>>2 [+8], col = (lane&3)*2 [+1])
    const int rowA = lane >> 2;
    const int colp = (lane & 3) * 2;
#pragma unroll
    for (int mf = 0; mf < 2; mf++)
#pragma unroll
        for (int nf = 0; nf < 8; nf++) {
            int m = row0 + wm * 32 + mf * 16 + rowA;
            int n = col0 + wn * 64 + nf * 8 + colp;
            store_pair<MODE, ISK>(m,     n, c[mf][nf][0], c[mf][nf][1], bias, outp);
            store_pair<MODE, ISK>(m + 8, n, c[mf][nf][2], c[mf][nf][3], bias, outp);
        }
}

// =====================================================================
// split helpers: fp32 -> (hi, lo) bf16
// =====================================================================
__device__ __forceinline__ void split_vec(float4 v, __nv_bfloat162* h2,
                                          __nv_bfloat162* l2, size_t i4)
{
    __nv_bfloat16 a = __float2bfloat16(v.x), b = __float2bfloat16(v.y);
    __nv_bfloat16 c = __float2bfloat16(v.z), d = __float2bfloat16(v.w);
    __nv_bfloat162 H0, H1, L0, L1;
    H0.x = a; H0.y = b; H1.x = c; H1.y = d;
    L0.x = __float2bfloat16(v.x - __bfloat162float(a));
    L0.y = __float2bfloat16(v.y - __bfloat162float(b));
    L1.x = __float2bfloat16(v.z - __bfloat162float(c));
    L1.y = __float2bfloat16(v.w - __bfloat162float(d));
    h2[2 * i4] = H0; h2[2 * i4 + 1] = H1;
    l2[2 * i4] = L0; l2[2 * i4 + 1] = L1;
}

__global__ void split_x_kernel(const float* __restrict__ x) {
    size_t i = (size_t)blockIdx.x * 256 + threadIdx.x;
    split_vec(((const float4*)x)[i], (__nv_bfloat162*)g_xhi, (__nv_bfloat162*)g_xlo, i);
}
__global__ void split_qk_kernel() {
    int z = blockIdx.y;
    const float* in = z ? g_k : g_q;
    __nv_bfloat162* h = (__nv_bfloat162*)(z ? g_khi : g_qhi);
    __nv_bfloat162* l = (__nv_bfloat162*)(z ? g_klo : g_qlo);
    size_t i = (size_t)blockIdx.x * 256 + threadIdx.x;
    split_vec(((const float4*)in)[i], h, l, i);
}
__global__ void split_attn_kernel() {
    size_t i = (size_t)blockIdx.x * 256 + threadIdx.x;
    split_vec(((const float4*)g_attn)[i], (__nv_bfloat162*)g_ahi, (__nv_bfloat162*)g_alo, i);
}
__global__ void split_wqkv_kernel(const float* __restrict__ Wq,
                                  const float* __restrict__ Wk,
                                  const float* __restrict__ Wv) {
    int z = blockIdx.y;
    const float* W = (z == 0) ? Wq : (z == 1) ? Wk : Wv;
    size_t i = (size_t)blockIdx.x * 256 + threadIdx.x;
    __nv_bfloat162* h = (__nv_bfloat162*)(g_wqkv_hi + (size_t)z * DD * DD);
    __nv_bfloat162* l = (__nv_bfloat162*)(g_wqkv_lo + (size_t)z * DD * DD);
    split_vec(((const float4*)W)[i], h, l, i);
}
__global__ void split_wo_kernel(const float* __restrict__ Wo) {
    size_t i = (size_t)blockIdx.x * 256 + threadIdx.x;
    split_vec(((const float4*)Wo)[i], (__nv_bfloat162*)g_wo_hi, (__nv_bfloat162*)g_wo_lo, i);
}
__global__ void split_proj_kernel(const float* __restrict__ p) {
    size_t i = (size_t)blockIdx.x * 256 + threadIdx.x;
    split_vec(((const float4*)p)[i], (__nv_bfloat162*)g_proj_hi, (__nv_bfloat162*)g_proj_lo, i);
}
__global__ void bias_cat_kernel(const float* __restrict__ bq,
                                const float* __restrict__ bk,
                                const float* __restrict__ bv) {
    int z = blockIdx.x;
    const float* b = (z == 0) ? bq : (z == 1) ? bk : bv;
    g_bqkv[z * DD + threadIdx.x] = b[threadIdx.x];
}

// =====================================================================
// fp32 kernels (unchanged from the passing round-7 baseline)
// =====================================================================
__global__ void diag_kernel()
{
    int z = blockIdx.y;
    const float* inp = z ? g_k : g_q;
    int warp = threadIdx.x >> 5, lane = threadIdx.x & 31;
    int r = blockIdx.x * 8 + warp;
    const float* p = inp + (size_t)r * DH;
    float a = p[lane], b = p[lane + 32];
    float s = a * a + b * b;
#pragma unroll
    for (int o = 16; o; o >>= 1) s += __shfl_xor_sync(0xffffffffu, s, o);
    if (lane == 0) g_diag[z * RR + r] = s * 0.0625f;
}

__global__ void rowmax_kernel()
{
    int z = blockIdx.y;
    const float* xp = z ? g_kp : g_qp;
    int warp = threadIdx.x >> 5, lane = threadIdx.x & 31;
    int r = blockIdx.x * 8 + warp;
    const float* p = xp + (size_t)r * MF;
    float mx = -1e30f;
#pragma unroll
    for (int i = 0; i < 8; i++) mx = fmaxf(mx, p[lane + i * 32]);
#pragma unroll
    for (int o = 16; o; o >>= 1) mx = fmaxf(mx, __shfl_xor_sync(0xffffffffu, mx, o));
    if (lane == 0) g_rmax[z * RR + r] = mx;
}

__global__ void kheadmax_kernel()
{
    int bh = blockIdx.x, tid = threadIdx.x;
    const float* p = g_rmax + RR + (size_t)bh * NN;
    float mx = -1e30f;
    for (int i = tid; i < NN; i += 256) mx = fmaxf(mx, p[i]);
    __shared__ float sm[256];
    sm[tid] = mx;
    __syncthreads();
    for (int s = 128; s > 0; s >>= 1) {
        if (tid < s) sm[tid] = fmaxf(sm[tid], sm[tid + s]);
        __syncthreads();
    }
    if (tid == 0) g_kmax[bh] = sm[0];
    g_ksum[bh * MF + tid] = 0.f;
}

__global__ void expphi_kernel()
{
    int isK = blockIdx.z;
    int bh  = blockIdx.y;
    int m   = threadIdx.x;
    int r0  = bh * NN + blockIdx.x * 256;
    float* buf = isK ? g_kp : g_qp;
    float headsub = isK ? g_kmax[bh] : 0.f;
    const float* diag = g_diag + (isK ? RR : 0);
    float acc = 0.f;
    for (int i = 0; i < 256; i++) {
        int r = r0 + i;
        float mv = isK ? headsub : g_rmax[r];
        size_t idx = (size_t)r * MF + m;
        float ph = 0.0625f * (expf(buf[idx] - diag[r] - mv) + 1e-4f);
        buf[idx] = ph;
        acc += ph;
    }
    if (isK) atomicAdd(&g_ksum[bh * MF + m], acc);
}

__global__ __launch_bounds__(256) void ctx_kernel()
{
    int bh = blockIdx.y;
    int m0 = blockIdx.x * 64;
    const float* kp = g_kp + (size_t)bh * NN * MF;
    const float* v  = g_v  + (size_t)bh * NN * DH;

    __shared__ float Ks[16][64];
    __shared__ float Vs[16][64];

    int tid = threadIdx.x;
    int kn  = tid >> 4;
    int c4  = (tid & 15) << 2;
    int ty  = tid >> 4, tx = tid & 15;

    float acc[4][4];
#pragma unroll
    for (int i = 0; i < 4; i++)
#pragma unroll
        for (int j = 0; j < 4; j++) acc[i][j] = 0.f;

    for (int n0 = 0; n0 < NN; n0 += 16) {
        *(float4*)&Ks[kn][c4] = *(const float4*)(kp + (size_t)(n0 + kn) * MF + m0 + c4);
        *(float4*)&Vs[kn][c4] = *(const float4*)(v  + (size_t)(n0 + kn) * DH + c4);
        __syncthreads();
#pragma unroll
        for (int k = 0; k < 16; k++) {
            float a[4], b[4];
            *(float4*)a = *(const float4*)&Ks[k][ty * 4];
            *(float4*)b = *(const float4*)&Vs[k][tx * 4];
#pragma unroll
            for (int i = 0; i < 4; i++)
#pragma unroll
                for (int j = 0; j < 4; j++) acc[i][j] += a[i] * b[j];
        }
        __syncthreads();
    }
#pragma unroll
    for (int i = 0; i < 4; i++) {
        float4 o = make_float4(acc[i][0], acc[i][1], acc[i][2], acc[i][3]);
        *(float4*)(g_ctx + ((size_t)bh * MF + m0 + ty * 4 + i) * DH + tx * 4) = o;
    }
}

__global__ void dden_kernel()
{
    int warp = threadIdx.x >> 5, lane = threadIdx.x & 31;
    int r  = blockIdx.x * 8 + warp;
    int bh = r >> 11;
    const float* qp = g_qp + (size_t)r * MF;
    const float* ks = g_ksum + bh * MF;
    float s = 0.f;
#pragma unroll
    for (int i = 0; i < 8; i++) s += qp[lane + i * 32] * ks[lane + i * 32];
#pragma unroll
    for (int o = 16; o; o >>= 1) s += __shfl_xor_sync(0xffffffffu, s, o);
    if (lane == 0) g_dinv[r] = 1.f / s;
}

__global__ __launch_bounds__(256) void outattn_kernel()
{
    int r0 = blockIdx.x * 64;
    int bh = r0 >> 11;
    const float* cx = g_ctx + (size_t)bh * MF * DH;

    __shared__ float As[16][68];
    __shared__ float Bs[16][64];

    int tid = threadIdx.x;
    int lr = tid >> 2;
    int lk = (tid & 3) << 2;
    int kn = tid >> 4;
    int c4 = (tid & 15) << 2;
    int ty = tid >> 4, tx = tid & 15;

    float acc[4][4];
#pragma unroll
    for (int i = 0; i < 4; i++)
#pragma unroll
        for (int j = 0; j < 4; j++) acc[i][j] = 0.f;

    for (int m0 = 0; m0 < MF; m0 += 16) {
        float4 fa = *(const float4*)(g_qp + (size_t)(r0 + lr) * MF + m0 + lk);
        As[lk + 0][lr] = fa.x; As[lk + 1][lr] = fa.y;
        As[lk + 2][lr] = fa.z; As[lk + 3][lr] = fa.w;
        *(float4*)&Bs[kn][c4] = *(const float4*)(cx + (size_t)(m0 + kn) * DH + c4);
        __syncthreads();
#pragma unroll
        for (int k = 0; k < 16; k++) {
            float a[4], b[4];
            *(float4*)a = *(const float4*)&As[k][ty * 4];
            *(float4*)b = *(const float4*)&Bs[k][tx * 4];
#pragma unroll
            for (int i = 0; i < 4; i++)
#pragma unroll
                for (int j = 0; j < 4; j++) acc[i][j] += a[i] * b[j];
        }
        __syncthreads();
    }

    int b = bh / HH;
    int h = bh - b * HH;
#pragma unroll
    for (int i = 0; i < 4; i++) {
        int r = r0 + ty * 4 + i;
        float di = g_dinv[r];
        int n = r & 2047;
        int t = b * NN + n;
        float4 o = make_float4(acc[i][0] * di, acc[i][1] * di,
                               acc[i][2] * di, acc[i][3] * di);
        *(float4*)(g_attn + (size_t)t * DD + h * DH + tx * 4) = o;
    }
}

// =====================================================================
extern "C" void kernel_launch(void* const* d_in, const int* in_sizes, int n_in,
                              void* d_out, int out_size)
{
    const float* x    = (const float*)d_in[0];
    const float* Wq   = (const float*)d_in[1];
    const float* bq   = (const float*)d_in[2];
    const float* Wk   = (const float*)d_in[3];
    const float* bk   = (const float*)d_in[4];
    const float* Wv   = (const float*)d_in[5];
    const float* bv   = (const float*)d_in[6];
    const float* Wo   = (const float*)d_in[7];
    const float* bo   = (const float*)d_in[8];
    const float* proj = (const float*)d_in[9];
    float* out = (float*)d_out;

    // input splits (memory-bound, cheap)
    split_wqkv_kernel<<<dim3(DD * DD / 1024, 3), 256>>>(Wq, Wk, Wv);
    split_wo_kernel<<<DD * DD / 1024, 256>>>(Wo);
    split_proj_kernel<<<MF * DH / 1024, 256>>>(proj);
    bias_cat_kernel<<<3, DD>>>(bq, bk, bv);
    split_x_kernel<<<TT * DD / 1024, 256>>>(x);

    // QKV projection (HMMA split bf16) -> g_q/g_k/g_v head layout
    mma_gemm<0, 0, 768><<<dim3(3 * DD / 128, TT / 128), 256>>>(nullptr, nullptr);

    diag_kernel<<<dim3(RR / 8, 2), 256>>>();
    split_qk_kernel<<<dim3(RR * DH / 1024, 2), 256>>>();

    // feature projections (HMMA) -> raw xp in g_qp / g_kp
    mma_gemm<2, 0, 64><<<dim3(MF / 128, RR / 128), 256>>>(nullptr, nullptr);
    mma_gemm<2, 1, 64><<<dim3(MF / 128, RR / 128), 256>>>(nullptr, nullptr);

    rowmax_kernel<<<dim3(RR / 8, 2), 256>>>();
    kheadmax_kernel<<<NBH, 256>>>();
    expphi_kernel<<<dim3(NN / 256, NBH, 2), 256>>>();
    ctx_kernel<<<dim3(MF / 64, NBH), 256>>>();
    dden_kernel<<<RR / 8, 256>>>();
    outattn_kernel<<<RR / 64, 256>>>();

    // output projection (HMMA)
    split_attn_kernel<<<TT * DD / 1024, 256>>>();
    mma_gemm<1, 0, 768><<<dim3(DD / 128, TT / 128), 256>>>(bo, out);
}

// round 14
// speedup vs baseline: 1.4675x; 1.0622x over previous
#include <cuda_runtime.h>
#include <cuda_bf16.h>
#include <math.h>
#include <stdint.h>

// ---------------- problem constants ----------------
#define BB   8
#define NN   2048
#define HH   12
#define DD   768
#define DH   64
#define MF   256
#define TT   16384            // B*N tokens
#define RR   196608           // B*H*N head-rows
#define NBH  96               // B*H

// ---------------- fp32 scratch ----------------
__device__ float g_qp[RR * MF];          // raw xp (q)
__device__ float g_kp[RR * MF];          // raw xp (k)
__device__ float g_diag[2 * RR];
__device__ float g_rmax[2 * RR];
__device__ float g_kmax[NBH];
__device__ float g_ksum[NBH * MF];
__device__ float g_dinv[RR];
__device__ float g_bqkv[3 * DD];

// ---------------- bf16 split scratch ----------------
__device__ __nv_bfloat16 g_xhi[TT * DD],  g_xlo[TT * DD];
__device__ __nv_bfloat16 g_wqkv_hi[3 * DD * DD], g_wqkv_lo[3 * DD * DD];
__device__ __nv_bfloat16 g_wo_hi[DD * DD], g_wo_lo[DD * DD];
__device__ __nv_bfloat16 g_proj_hi[MF * DH], g_proj_lo[MF * DH];
__device__ __nv_bfloat16 g_qhi[RR * DH], g_qlo[RR * DH];
__device__ __nv_bfloat16 g_khi[RR * DH], g_klo[RR * DH];
__device__ __nv_bfloat16 g_vhi[RR * DH], g_vlo[RR * DH];
__device__ __nv_bfloat16 g_ahi[TT * DD], g_alo[TT * DD];
__device__ __nv_bfloat16 g_qp_h[RR * MF], g_qp_l[RR * MF];   // phi(q) split
__device__ __nv_bfloat16 g_kp_h[RR * MF], g_kp_l[RR * MF];   // phi(k) split
__device__ __nv_bfloat16 g_ctx_h[NBH * MF * DH], g_ctx_l[NBH * MF * DH];

// =====================================================================
// helpers (base-ISA only: ldmatrix / mma.sync / cp.async)
// =====================================================================
__device__ __forceinline__ uint32_t smem_u32(const void* p) {
    uint32_t a;
    asm("{ .reg .u64 t; cvta.to.shared.u64 t, %1; cvt.u32.u64 %0, t; }" : "=r"(a) : "l"(p));
    return a;
}

#define LDSM4(r, addr) \
    asm volatile("ldmatrix.sync.aligned.m8n8.x4.shared.b16 {%0,%1,%2,%3}, [%4];" \
        : "=r"((r)[0]), "=r"((r)[1]), "=r"((r)[2]), "=r"((r)[3]) : "r"(addr))

#define LDSM4T(r, addr) \
    asm volatile("ldmatrix.sync.aligned.m8n8.x4.trans.shared.b16 {%0,%1,%2,%3}, [%4];" \
        : "=r"((r)[0]), "=r"((r)[1]), "=r"((r)[2]), "=r"((r)[3]) : "r"(addr))

#define MMA16816(c, a, b0, b1) \
    asm volatile("mma.sync.aligned.m16n8k16.row.col.f32.bf16.bf16.f32 " \
        "{%0,%1,%2,%3}, {%4,%5,%6,%7}, {%8,%9}, {%0,%1,%2,%3};" \
        : "+f"((c)[0]), "+f"((c)[1]), "+f"((c)[2]), "+f"((c)[3]) \
        : "r"((a)[0]), "r"((a)[1]), "r"((a)[2]), "r"((a)[3]), "r"(b0), "r"(b1))

#define CP_ASYNC16(saddr, gptr) \
    asm volatile("cp.async.cg.shared.global [%0], [%1], 16;" :: "r"(saddr), "l"(gptr))
#define CP_COMMIT() asm volatile("cp.async.commit_group;" ::: "memory")

// split a float pair and store hi/lo bf16x2
__device__ __forceinline__ void store_split2(__nv_bfloat16* hp, __nv_bfloat16* lp,
                                             size_t idx, float v0, float v1) {
    __nv_bfloat16 h0 = __float2bfloat16(v0), h1 = __float2bfloat16(v1);
    __nv_bfloat162 H; H.x = h0; H.y = h1;
    __nv_bfloat162 L;
    L.x = __float2bfloat16(v0 - __bfloat162float(h0));
    L.y = __float2bfloat16(v1 - __bfloat162float(h1));
    *(__nv_bfloat162*)(hp + idx) = H;
    *(__nv_bfloat162*)(lp + idx) = L;
}

// =====================================================================
// per-MODE epilogue store of a (v0, v1) pair at logical (t, c)
// =====================================================================
template<int MODE, int ISK>
__device__ __forceinline__ void store_pair(int t, int c, float v0, float v1,
                                           const float* __restrict__ bias,
                                           float* __restrict__ outp)
{
    if (MODE == 0) {
        int seg = c / DD; int oc = c - seg * DD;
        int h = oc >> 6, d0 = oc & 63;
        __nv_bfloat16 *oph, *opl;
        if (seg == 0)      { oph = g_qhi; opl = g_qlo; }
        else if (seg == 1) { oph = g_khi; opl = g_klo; }
        else               { oph = g_vhi; opl = g_vlo; }
        int bT = t >> 11, n = t & 2047;
        size_t base = (((size_t)(bT * HH + h)) * NN + n) * DH + d0;
        store_split2(oph, opl, base, v0 + g_bqkv[c], v1 + g_bqkv[c + 1]);
    } else if (MODE == 1) {
        *(float2*)(outp + (size_t)t * DD + c) =
            make_float2(v0 + bias[c], v1 + bias[c + 1]);
    } else {
        const float dnv = 0.35355339059327373f;   // 64^-0.25
        float* dst = ISK ? g_kp : g_qp;
        *(float2*)(dst + (size_t)t * MF + c) = make_float2(v0 * dnv, v1 * dnv);
    }
}

// =====================================================================
// split-fp32 HMMA GEMM (unchanged structure from passing R13 kernel)
// K concat = 3*KD segments: [Ahi|Alo|Ahi] x [Bhi|Bhi|Blo]
// 128x128 CTA tile, BK=32, 8 warps (4m x 2n), warp tile 32x64.
// =====================================================================
template<int MODE, int ISK, int KD>
__global__ __launch_bounds__(256) void mma_gemm(const float* __restrict__ bias,
                                                float* __restrict__ outp)
{
    __shared__ __nv_bfloat16 shA[2 * 128 * 40];
    __shared__ __nv_bfloat16 shB[2 * 128 * 40];

    const int tid  = threadIdx.x;
    const int lane = tid & 31;
    const int wid  = tid >> 5;
    const int wm   = wid & 3;
    const int wn   = wid >> 2;
    const int row0 = blockIdx.y * 128;
    const int col0 = blockIdx.x * 128;

    const __nv_bfloat16 *Ahi, *Alo, *Bhi, *Blo;
    if (MODE == 0)      { Ahi = g_xhi; Alo = g_xlo; Bhi = g_wqkv_hi; Blo = g_wqkv_lo; }
    else if (MODE == 1) { Ahi = g_ahi; Alo = g_alo; Bhi = g_wo_hi;   Blo = g_wo_lo;   }
    else                { Ahi = ISK ? g_khi : g_qhi; Alo = ISK ? g_klo : g_qlo;
                          Bhi = g_proj_hi; Blo = g_proj_lo; }

    const uint32_t smA = smem_u32(shA);
    const uint32_t smB = smem_u32(shB);

    const int rowL  = tid >> 1;
    const int halfE = (tid & 1) * 16;

    const int numT = 3 * KD / 32;

#define LOAD_TILE(I, BUF) do {                                                   \
        int kcat = (I) * 32; int seg = kcat / KD; int koff = kcat - seg * KD;    \
        const __nv_bfloat16* Ap = (seg == 1) ? Alo : Ahi;                        \
        const __nv_bfloat16* Bp = (seg == 2) ? Blo : Bhi;                        \
        const __nv_bfloat16* ag = Ap + (size_t)(row0 + rowL) * KD + koff + halfE; \
        const __nv_bfloat16* bg = Bp + (size_t)(col0 + rowL) * KD + koff + halfE; \
        uint32_t sa  = smA + ((BUF) * 128 * 40 + rowL * 40 + halfE) * 2;         \
        uint32_t sbv = smB + ((BUF) * 128 * 40 + rowL * 40 + halfE) * 2;         \
        CP_ASYNC16(sa,       ag);                                                \
        CP_ASYNC16(sa  + 16, ag + 8);                                            \
        CP_ASYNC16(sbv,      bg);                                                \
        CP_ASYNC16(sbv + 16, bg + 8);                                            \
    } while (0)

    float c[2][8][4];
#pragma unroll
    for (int mf = 0; mf < 2; mf++)
#pragma unroll
        for (int nf = 0; nf < 8; nf++)
#pragma unroll
            for (int j = 0; j < 4; j++) c[mf][nf][j] = 0.f;

    LOAD_TILE(0, 0);
    CP_COMMIT();

    const int lrow = lane & 15;
    const int lcol = (lane >> 4) << 3;

    for (int i = 0; i < numT; i++) {
        if (i + 1 < numT) {
            LOAD_TILE(i + 1, (i + 1) & 1);
            CP_COMMIT();
            asm volatile("cp.async.wait_group 1;" ::: "memory");
        } else {
            asm volatile("cp.async.wait_group 0;" ::: "memory");
        }
        __syncthreads();

        const int buf = i & 1;
        const uint32_t baseA = smA + buf * (128 * 40 * 2);
        const uint32_t baseB = smB + buf * (128 * 40 * 2);

#pragma unroll
        for (int k16 = 0; k16 < 32; k16 += 16) {
            uint32_t a[2][4], bq[4][4];
#pragma unroll
            for (int mf = 0; mf < 2; mf++) {
                uint32_t ad = baseA + ((wm * 32 + mf * 16 + lrow) * 40 + k16 + lcol) * 2;
                LDSM4(a[mf], ad);
            }
#pragma unroll
            for (int nf4 = 0; nf4 < 4; nf4++) {
                uint32_t bd = baseB + ((wn * 64 + nf4 * 16 + lrow) * 40 + k16 + lcol) * 2;
                LDSM4(bq[nf4], bd);
            }
#pragma unroll
            for (int mf = 0; mf < 2; mf++)
#pragma unroll
                for (int nf4 = 0; nf4 < 4; nf4++) {
                    MMA16816(c[mf][nf4 * 2],     a[mf], bq[nf4][0], bq[nf4][2]);
                    MMA16816(c[mf][nf4 * 2 + 1], a[mf], bq[nf4][1], bq[nf4][3]);
                }
        }
        __syncthreads();
    }
#undef LOAD_TILE

    const int rowA = lane >> 2;
    const int colp = (lane & 3) * 2;
#pragma unroll
    for (int mf = 0; mf < 2; mf++)
#pragma unroll
        for (int nf = 0; nf < 8; nf++) {
            int m = row0 + wm * 32 + mf * 16 + rowA;
            int n = col0 + wn * 64 + nf * 8 + colp;
            store_pair<MODE, ISK>(m,     n, c[mf][nf][0], c[mf][nf][1], bias, outp);
            store_pair<MODE, ISK>(m + 8, n, c[mf][nf][2], c[mf][nf][3], bias, outp);
        }
}

// =====================================================================
// ctx HMMA: ctx[bh][m][d] = sum_n kp[bh][n][m] * v[bh][n][d]
// A = kp (memory [n][m] -> trans loads), B = v (memory [n][d] -> trans).
// 3-term split, K concat = 3*NN. CTA tile 128(m) x 64(d), 8 warps 32x32.
// grid (2, NBH). Writes ctx hi/lo bf16.
// =====================================================================
__global__ __launch_bounds__(256) void ctx_mma()
{
    __shared__ __nv_bfloat16 shA[2 * 32 * 136];   // kp tile [n=32][m=128 (+8)]
    __shared__ __nv_bfloat16 shV[2 * 32 * 72];    // v  tile [n=32][d=64 (+8)]

    const int tid = threadIdx.x, lane = tid & 31, wid = tid >> 5;
    const int wm = wid & 3, wn = wid >> 2;
    const int bh = blockIdx.y;
    const int m0 = blockIdx.x * 128;

    const __nv_bfloat16* kph = g_kp_h + (size_t)bh * NN * MF;
    const __nv_bfloat16* kpl = g_kp_l + (size_t)bh * NN * MF;
    const __nv_bfloat16* vhp = g_vhi + (size_t)bh * NN * DH;
    const __nv_bfloat16* vlp = g_vlo + (size_t)bh * NN * DH;

    const uint32_t smA = smem_u32(shA);
    const uint32_t smV = smem_u32(shV);

    const int arow = tid >> 3, achk = tid & 7;
    const int numT = 3 * NN / 32;   // 192

#define CTX_LOAD(I, BUF) do {                                                    \
        int kc = (I) * 32; int seg = kc / NN; int noff = kc - seg * NN;          \
        const __nv_bfloat16* Ap = (seg == 1) ? kpl : kph;                        \
        const __nv_bfloat16* Vp = (seg == 2) ? vlp : vhp;                        \
        const __nv_bfloat16* ag = Ap + (size_t)(noff + arow) * MF + m0 + achk * 8; \
        uint32_t sa = smA + ((BUF) * 32 * 136 + arow * 136 + achk * 8) * 2;      \
        CP_ASYNC16(sa,       ag);                                                \
        CP_ASYNC16(sa + 128, ag + 64);                                           \
        const __nv_bfloat16* vg = Vp + (size_t)(noff + arow) * DH + achk * 8;    \
        uint32_t sv = smV + ((BUF) * 32 * 72 + arow * 72 + achk * 8) * 2;        \
        CP_ASYNC16(sv, vg);                                                      \
    } while (0)

    float c[2][4][4];
#pragma unroll
    for (int mf = 0; mf < 2; mf++)
#pragma unroll
        for (int nf = 0; nf < 4; nf++)
#pragma unroll
            for (int j = 0; j < 4; j++) c[mf][nf][j] = 0.f;

    CTX_LOAD(0, 0);
    CP_COMMIT();

    const int trow = lane & 7;
    const int tm8  = ((lane >> 3) & 1) * 8;   // +8 in the transposed (col) dim
    const int tk8  = ((lane >> 4) & 1) * 8;   // +8 in k

    for (int i = 0; i < numT; i++) {
        if (i + 1 < numT) {
            CTX_LOAD(i + 1, (i + 1) & 1);
            CP_COMMIT();
            asm volatile("cp.async.wait_group 1;" ::: "memory");
        } else {
            asm volatile("cp.async.wait_group 0;" ::: "memory");
        }
        __syncthreads();

        const int buf = i & 1;
        const uint32_t baseA = smA + buf * (32 * 136 * 2);
        const uint32_t baseV = smV + buf * (32 * 72 * 2);

#pragma unroll
        for (int k16 = 0; k16 < 32; k16 += 16) {
            uint32_t a[2][4], bq[2][4];
#pragma unroll
            for (int mf = 0; mf < 2; mf++) {
                uint32_t ad = baseA + ((k16 + trow + tk8) * 136 + wm * 32 + mf * 16 + tm8) * 2;
                LDSM4T(a[mf], ad);
            }
#pragma unroll
            for (int nf = 0; nf < 2; nf++) {
                uint32_t bd = baseV + ((k16 + trow + tk8) * 72 + wn * 32 + nf * 16 + tm8) * 2;
                LDSM4T(bq[nf], bd);
            }
#pragma unroll
            for (int mf = 0; mf < 2; mf++)
#pragma unroll
                for (int nf = 0; nf < 2; nf++) {
                    MMA16816(c[mf][nf * 2],     a[mf], bq[nf][0], bq[nf][2]);
                    MMA16816(c[mf][nf * 2 + 1], a[mf], bq[nf][1], bq[nf][3]);
                }
        }
        __syncthreads();
    }
#undef CTX_LOAD

    const int rowA = lane >> 2, colp = (lane & 3) * 2;
#pragma unroll
    for (int mf = 0; mf < 2; mf++)
#pragma unroll
        for (int blk = 0; blk < 4; blk++) {
            int m = m0 + wm * 32 + mf * 16 + rowA;
            int d = wn * 32 + blk * 8 + colp;
            size_t b0 = ((size_t)bh * MF + m) * DH + d;
            store_split2(g_ctx_h, g_ctx_l, b0,            c[mf][blk][0], c[mf][blk][1]);
            store_split2(g_ctx_h, g_ctx_l, b0 + 8 * DH,   c[mf][blk][2], c[mf][blk][3]);
        }
}

// =====================================================================
// outattn HMMA: out[r][d] = dinv[r] * sum_m qp[r][m] * ctx[bh][m][d]
// A = qp (memory [r][m], non-trans), B = ctx (memory [m][d] -> trans).
// 3-term split, K concat = 3*MF = 768. CTA 128(r) x 64(d), grid RR/128.
// Writes attn hi/lo bf16 in token layout.
// =====================================================================
__global__ __launch_bounds__(256) void outattn_mma()
{
    __shared__ __nv_bfloat16 shA[2 * 128 * 40];   // qp tile [r=128][m=32 (+8)]
    __shared__ __nv_bfloat16 shB[2 * 32 * 72];    // ctx tile [m=32][d=64 (+8)]

    const int tid = threadIdx.x, lane = tid & 31, wid = tid >> 5;
    const int wm = wid & 3, wn = wid >> 2;
    const int r0 = blockIdx.x * 128;
    const int bh = r0 >> 11;

    const __nv_bfloat16* cth = g_ctx_h + (size_t)bh * MF * DH;
    const __nv_bfloat16* ctl = g_ctx_l + (size_t)bh * MF * DH;

    const uint32_t smA = smem_u32(shA);
    const uint32_t smB = smem_u32(shB);

    const int rowL = tid >> 1, halfE = (tid & 1) * 16;
    const int brow = tid >> 3, bchk = tid & 7;
    const int numT = 3 * MF / 32;   // 24

#define OA_LOAD(I, BUF) do {                                                     \
        int kc = (I) * 32; int seg = kc / MF; int moff = kc - seg * MF;          \
        const __nv_bfloat16* Ap = (seg == 1) ? g_qp_l : g_qp_h;                  \
        const __nv_bfloat16* Bp = (seg == 2) ? ctl : cth;                        \
        const __nv_bfloat16* ag = Ap + (size_t)(r0 + rowL) * MF + moff + halfE;  \
        uint32_t sa = smA + ((BUF) * 128 * 40 + rowL * 40 + halfE) * 2;          \
        CP_ASYNC16(sa,      ag);                                                 \
        CP_ASYNC16(sa + 16, ag + 8);                                             \
        const __nv_bfloat16* bg = Bp + (size_t)(moff + brow) * DH + bchk * 8;    \
        uint32_t sb = smB + ((BUF) * 32 * 72 + brow * 72 + bchk * 8) * 2;        \
        CP_ASYNC16(sb, bg);                                                      \
    } while (0)

    float c[2][4][4];
#pragma unroll
    for (int mf = 0; mf < 2; mf++)
#pragma unroll
        for (int nf = 0; nf < 4; nf++)
#pragma unroll
            for (int j = 0; j < 4; j++) c[mf][nf][j] = 0.f;

    OA_LOAD(0, 0);
    CP_COMMIT();

    const int lrow = lane & 15;
    const int lcol = (lane >> 4) << 3;
    const int trow = lane & 7;
    const int tm8  = ((lane >> 3) & 1) * 8;
    const int tk8  = ((lane >> 4) & 1) * 8;

    for (int i = 0; i < numT; i++) {
        if (i + 1 < numT) {
            OA_LOAD(i + 1, (i + 1) & 1);
            CP_COMMIT();
            asm volatile("cp.async.wait_group 1;" ::: "memory");
        } else {
            asm volatile("cp.async.wait_group 0;" ::: "memory");
        }
        __syncthreads();

        const int buf = i & 1;
        const uint32_t baseA = smA + buf * (128 * 40 * 2);
        const uint32_t baseB = smB + buf * (32 * 72 * 2);

#pragma unroll
        for (int k16 = 0; k16 < 32; k16 += 16) {
            uint32_t a[2][4], bq[2][4];
#pragma unroll
            for (int mf = 0; mf < 2; mf++) {
                uint32_t ad = baseA + ((wm * 32 + mf * 16 + lrow) * 40 + k16 + lcol) * 2;
                LDSM4(a[mf], ad);
            }
#pragma unroll
            for (int nf = 0; nf < 2; nf++) {
                uint32_t bd = baseB + ((k16 + trow + tk8) * 72 + wn * 32 + nf * 16 + tm8) * 2;
                LDSM4T(bq[nf], bd);
            }
#pragma unroll
            for (int mf = 0; mf < 2; mf++)
#pragma unroll
                for (int nf = 0; nf < 2; nf++) {
                    MMA16816(c[mf][nf * 2],     a[mf], bq[nf][0], bq[nf][2]);
                    MMA16816(c[mf][nf * 2 + 1], a[mf], bq[nf][1], bq[nf][3]);
                }
        }
        __syncthreads();
    }
#undef OA_LOAD

    const int rowA = lane >> 2, colp = (lane & 3) * 2;
    const int b = bh / HH, h = bh - b * HH;
#pragma unroll
    for (int mf = 0; mf < 2; mf++)
#pragma unroll
        for (int blk = 0; blk < 4; blk++) {
            int r = r0 + wm * 32 + mf * 16 + rowA;
            int d = wn * 32 + blk * 8 + colp;
            {
                float di = g_dinv[r];
                int t = b * NN + (r & 2047);
                store_split2(g_ahi, g_alo, (size_t)t * DD + h * DH + d,
                             c[mf][blk][0] * di, c[mf][blk][1] * di);
            }
            {
                int r2 = r + 8;
                float di = g_dinv[r2];
                int t = b * NN + (r2 & 2047);
                store_split2(g_ahi, g_alo, (size_t)t * DD + h * DH + d,
                             c[mf][blk][2] * di, c[mf][blk][3] * di);
            }
        }
}

// =====================================================================
// split helpers: fp32 -> (hi, lo) bf16
// =====================================================================
__device__ __forceinline__ void split_vec(float4 v, __nv_bfloat162* h2,
                                          __nv_bfloat162* l2, size_t i4)
{
    __nv_bfloat16 a = __float2bfloat16(v.x), b = __float2bfloat16(v.y);
    __nv_bfloat16 c = __float2bfloat16(v.z), d = __float2bfloat16(v.w);
    __nv_bfloat162 H0, H1, L0, L1;
    H0.x = a; H0.y = b; H1.x = c; H1.y = d;
    L0.x = __float2bfloat16(v.x - __bfloat162float(a));
    L0.y = __float2bfloat16(v.y - __bfloat162float(b));
    L1.x = __float2bfloat16(v.z - __bfloat162float(c));
    L1.y = __float2bfloat16(v.w - __bfloat162float(d));
    h2[2 * i4] = H0; h2[2 * i4 + 1] = H1;
    l2[2 * i4] = L0; l2[2 * i4 + 1] = L1;
}

__global__ void split_x_kernel(const float* __restrict__ x) {
    size_t i = (size_t)blockIdx.x * 256 + threadIdx.x;
    split_vec(((const float4*)x)[i], (__nv_bfloat162*)g_xhi, (__nv_bfloat162*)g_xlo, i);
}
__global__ void split_wqkv_kernel(const float* __restrict__ Wq,
                                  const float* __restrict__ Wk,
                                  const float* __restrict__ Wv) {
    int z = blockIdx.y;
    const float* W = (z == 0) ? Wq : (z == 1) ? Wk : Wv;
    size_t i = (size_t)blockIdx.x * 256 + threadIdx.x;
    __nv_bfloat162* h = (__nv_bfloat162*)(g_wqkv_hi + (size_t)z * DD * DD);
    __nv_bfloat162* l = (__nv_bfloat162*)(g_wqkv_lo + (size_t)z * DD * DD);
    split_vec(((const float4*)W)[i], h, l, i);
}
__global__ void split_wo_kernel(const float* __restrict__ Wo) {
    size_t i = (size_t)blockIdx.x * 256 + threadIdx.x;
    split_vec(((const float4*)Wo)[i], (__nv_bfloat162*)g_wo_hi, (__nv_bfloat162*)g_wo_lo, i);
}
__global__ void split_proj_kernel(const float* __restrict__ p) {
    size_t i = (size_t)blockIdx.x * 256 + threadIdx.x;
    split_vec(((const float4*)p)[i], (__nv_bfloat162*)g_proj_hi, (__nv_bfloat162*)g_proj_lo, i);
}
__global__ void bias_cat_kernel(const float* __restrict__ bq,
                                const float* __restrict__ bk,
                                const float* __restrict__ bv) {
    int z = blockIdx.x;
    const float* b = (z == 0) ? bq : (z == 1) ? bk : bv;
    g_bqkv[z * DD + threadIdx.x] = b[threadIdx.x];
}

// =====================================================================
// small fp32 kernels
// =====================================================================
__global__ void diag_kernel()
{
    int z = blockIdx.y;
    const __nv_bfloat16* ph = (z ? g_khi : g_qhi);
    const __nv_bfloat16* pl = (z ? g_klo : g_qlo);
    int warp = threadIdx.x >> 5, lane = threadIdx.x & 31;
    int r = blockIdx.x * 8 + warp;
    size_t base = (size_t)r * DH;
    float a = __bfloat162float(ph[base + lane])      + __bfloat162float(pl[base + lane]);
    float b = __bfloat162float(ph[base + lane + 32]) + __bfloat162float(pl[base + lane + 32]);
    float s = a * a + b * b;
#pragma unroll
    for (int o = 16; o; o >>= 1) s += __shfl_xor_sync(0xffffffffu, s, o);
    if (lane == 0) g_diag[z * RR + r] = s * 0.0625f;
}

__global__ void rowmax_kernel()
{
    int z = blockIdx.y;
    const float* xp = z ? g_kp : g_qp;
    int warp = threadIdx.x >> 5, lane = threadIdx.x & 31;
    int r = blockIdx.x * 8 + warp;
    const float* p = xp + (size_t)r * MF;
    float mx = -1e30f;
#pragma unroll
    for (int i = 0; i < 8; i++) mx = fmaxf(mx, p[lane + i * 32]);
#pragma unroll
    for (int o = 16; o; o >>= 1) mx = fmaxf(mx, __shfl_xor_sync(0xffffffffu, mx, o));
    if (lane == 0) g_rmax[z * RR + r] = mx;
}

__global__ void kheadmax_kernel()
{
    int bh = blockIdx.x, tid = threadIdx.x;
    const float* p = g_rmax + RR + (size_t)bh * NN;
    float mx = -1e30f;
    for (int i = tid; i < NN; i += 256) mx = fmaxf(mx, p[i]);
    __shared__ float sm[256];
    sm[tid] = mx;
    __syncthreads();
    for (int s = 128; s > 0; s >>= 1) {
        if (tid < s) sm[tid] = fmaxf(sm[tid], sm[tid + s]);
        __syncthreads();
    }
    if (tid == 0) g_kmax[bh] = sm[0];
    g_ksum[bh * MF + tid] = 0.f;
}

// phi = ratio*(exp(xp - diag - m) + eps); writes hi/lo bf16 split.
__global__ void expphi_kernel()
{
    int isK = blockIdx.z;
    int bh  = blockIdx.y;
    int m   = threadIdx.x;
    int r0  = bh * NN + blockIdx.x * 256;
    const float* buf = isK ? g_kp : g_qp;
    __nv_bfloat16* oh = isK ? g_kp_h : g_qp_h;
    __nv_bfloat16* ol = isK ? g_kp_l : g_qp_l;
    float headsub = isK ? g_kmax[bh] : 0.f;
    const float* diag = g_diag + (isK ? RR : 0);
    float acc = 0.f;
    for (int i = 0; i < 256; i++) {
        int r = r0 + i;
        float mv = isK ? headsub : g_rmax[r];
        size_t idx = (size_t)r * MF + m;
        float ph = 0.0625f * (expf(buf[idx] - diag[r] - mv) + 1e-4f);
        __nv_bfloat16 hh = __float2bfloat16(ph);
        oh[idx] = hh;
        ol[idx] = __float2bfloat16(ph - __bfloat162float(hh));
        acc += ph;
    }
    if (isK) atomicAdd(&g_ksum[bh * MF + m], acc);
}

__global__ void dden_kernel()
{
    int warp = threadIdx.x >> 5, lane = threadIdx.x & 31;
    int r  = blockIdx.x * 8 + warp;
    int bh = r >> 11;
    const __nv_bfloat16* qh = g_qp_h + (size_t)r * MF;
    const __nv_bfloat16* ql = g_qp_l + (size_t)r * MF;
    const float* ks = g_ksum + bh * MF;
    float s = 0.f;
#pragma unroll
    for (int i = 0; i < 8; i++) {
        int j = lane + i * 32;
        float qv = __bfloat162float(qh[j]) + __bfloat162float(ql[j]);
        s += qv * ks[j];
    }
#pragma unroll
    for (int o = 16; o; o >>= 1) s += __shfl_xor_sync(0xffffffffu, s, o);
    if (lane == 0) g_dinv[r] = 1.f / s;
}

// =====================================================================
extern "C" void kernel_launch(void* const* d_in, const int* in_sizes, int n_in,
                              void* d_out, int out_size)
{
    const float* x    = (const float*)d_in[0];
    const float* Wq   = (const float*)d_in[1];
    const float* bq   = (const float*)d_in[2];
    const float* Wk   = (const float*)d_in[3];
    const float* bk   = (const float*)d_in[4];
    const float* Wv   = (const float*)d_in[5];
    const float* bv   = (const float*)d_in[6];
    const float* Wo   = (const float*)d_in[7];
    const float* bo   = (const float*)d_in[8];
    const float* proj = (const float*)d_in[9];
    float* out = (float*)d_out;

    // input splits
    split_wqkv_kernel<<<dim3(DD * DD / 1024, 3), 256>>>(Wq, Wk, Wv);
    split_wo_kernel<<<DD * DD / 1024, 256>>>(Wo);
    split_proj_kernel<<<MF * DH / 1024, 256>>>(proj);
    bias_cat_kernel<<<3, DD>>>(bq, bk, bv);
    split_x_kernel<<<TT * DD / 1024, 256>>>(x);

    // QKV projection -> q/k/v hi/lo bf16 head layout
    mma_gemm<0, 0, 768><<<dim3(3 * DD / 128, TT / 128), 256>>>(nullptr, nullptr);

    diag_kernel<<<dim3(RR / 8, 2), 256>>>();

    // feature projections -> raw xp fp32 in g_qp / g_kp
    mma_gemm<2, 0, 64><<<dim3(MF / 128, RR / 128), 256>>>(nullptr, nullptr);
    mma_gemm<2, 1, 64><<<dim3(MF / 128, RR / 128), 256>>>(nullptr, nullptr);

    rowmax_kernel<<<dim3(RR / 8, 2), 256>>>();
    kheadmax_kernel<<<NBH, 256>>>();
    expphi_kernel<<<dim3(NN / 256, NBH, 2), 256>>>();

    // ctx = kp^T @ v  (HMMA, trans loads) -> ctx hi/lo
    ctx_mma<<<dim3(2, NBH), 256>>>();

    dden_kernel<<<RR / 8, 256>>>();

    // out_attn = (qp @ ctx) * dinv (HMMA) -> attn hi/lo token layout
    outattn_mma<<<RR / 128, 256>>>();

    // output projection
    mma_gemm<1, 0, 768><<<dim3(DD / 128, TT / 128), 256>>>(bo, out);
}

// round 15
// speedup vs baseline: 1.5587x; 1.0622x over previous
#include <cuda_runtime.h>
#include <cuda_bf16.h>
#include <math.h>
#include <stdint.h>

// ---------------- problem constants ----------------
#define BB   8
#define NN   2048
#define HH   12
#define DD   768
#define DH   64
#define MF   256
#define TT   16384            // B*N tokens
#define RR   196608           // B*H*N head-rows
#define NBH  96               // B*H

// ---------------- fp32 scratch ----------------
__device__ float g_qp[RR * MF];          // raw xp (q)
__device__ float g_kp[RR * MF];          // raw xp (k)
__device__ float g_diag[2 * RR];
__device__ float g_rmax[RR];             // per-row max of raw xp (k only)
__device__ float g_kmax[NBH];
__device__ float g_ksum[NBH * MF];
__device__ float g_dinv[RR];
__device__ float g_bqkv[3 * DD];

// ---------------- bf16 split scratch ----------------
__device__ __nv_bfloat16 g_xhi[TT * DD],  g_xlo[TT * DD];
__device__ __nv_bfloat16 g_wqkv_hi[3 * DD * DD], g_wqkv_lo[3 * DD * DD];
__device__ __nv_bfloat16 g_wo_hi[DD * DD], g_wo_lo[DD * DD];
__device__ __nv_bfloat16 g_proj_hi[MF * DH], g_proj_lo[MF * DH];
__device__ __nv_bfloat16 g_qhi[RR * DH], g_qlo[RR * DH];
__device__ __nv_bfloat16 g_khi[RR * DH], g_klo[RR * DH];
__device__ __nv_bfloat16 g_vhi[RR * DH], g_vlo[RR * DH];
__device__ __nv_bfloat16 g_ahi[TT * DD], g_alo[TT * DD];
__device__ __nv_bfloat16 g_qp_h[RR * MF], g_qp_l[RR * MF];   // phi(q) split
__device__ __nv_bfloat16 g_kp_h[RR * MF], g_kp_l[RR * MF];   // phi(k) split
__device__ __nv_bfloat16 g_ctx_h[NBH * MF * DH], g_ctx_l[NBH * MF * DH];

// =====================================================================
// helpers (base-ISA only: ldmatrix / mma.sync / cp.async)
// =====================================================================
__device__ __forceinline__ uint32_t smem_u32(const void* p) {
    uint32_t a;
    asm("{ .reg .u64 t; cvta.to.shared.u64 t, %1; cvt.u32.u64 %0, t; }" : "=r"(a) : "l"(p));
    return a;
}

#define LDSM4(r, addr) \
    asm volatile("ldmatrix.sync.aligned.m8n8.x4.shared.b16 {%0,%1,%2,%3}, [%4];" \
        : "=r"((r)[0]), "=r"((r)[1]), "=r"((r)[2]), "=r"((r)[3]) : "r"(addr))

#define LDSM4T(r, addr) \
    asm volatile("ldmatrix.sync.aligned.m8n8.x4.trans.shared.b16 {%0,%1,%2,%3}, [%4];" \
        : "=r"((r)[0]), "=r"((r)[1]), "=r"((r)[2]), "=r"((r)[3]) : "r"(addr))

#define MMA16816(c, a, b0, b1) \
    asm volatile("mma.sync.aligned.m16n8k16.row.col.f32.bf16.bf16.f32 " \
        "{%0,%1,%2,%3}, {%4,%5,%6,%7}, {%8,%9}, {%0,%1,%2,%3};" \
        : "+f"((c)[0]), "+f"((c)[1]), "+f"((c)[2]), "+f"((c)[3]) \
        : "r"((a)[0]), "r"((a)[1]), "r"((a)[2]), "r"((a)[3]), "r"(b0), "r"(b1))

#define CP_ASYNC16(saddr, gptr) \
    asm volatile("cp.async.cg.shared.global [%0], [%1], 16;" :: "r"(saddr), "l"(gptr))
#define CP_COMMIT() asm volatile("cp.async.commit_group;" ::: "memory")

// fast exp on the FMA pipe (no MUFU). Valid for x <= ~0 (our case);
// underflow clamped. abs err ~1e-7.
__device__ __forceinline__ float fexp(float x) {
    float t = x * 1.4426950408889634f;     // log2(e)
    float n = rintf(t);
    float f = t - n;                        // [-0.5, 0.5]
    float p = 1.54035303933816e-4f;
    p = fmaf(p, f, 1.33335581464284e-3f);
    p = fmaf(p, f, 9.61812910762848e-3f);
    p = fmaf(p, f, 5.55041086648216e-2f);
    p = fmaf(p, f, 2.40226506959101e-1f);
    p = fmaf(p, f, 6.93147180559945e-1f);
    p = fmaf(p, f, 1.0f);
    int ni = (int)n;
    ni = ni < -126 ? -126 : ni;
    float s = __int_as_float((uint32_t)(ni + 127) << 23);
    return p * s;
}

// split a float pair and store hi/lo bf16x2
__device__ __forceinline__ void store_split2(__nv_bfloat16* hp, __nv_bfloat16* lp,
                                             size_t idx, float v0, float v1) {
    __nv_bfloat16 h0 = __float2bfloat16(v0), h1 = __float2bfloat16(v1);
    __nv_bfloat162 H; H.x = h0; H.y = h1;
    __nv_bfloat162 L;
    L.x = __float2bfloat16(v0 - __bfloat162float(h0));
    L.y = __float2bfloat16(v1 - __bfloat162float(h1));
    *(__nv_bfloat162*)(hp + idx) = H;
    *(__nv_bfloat162*)(lp + idx) = L;
}

// =====================================================================
// per-MODE epilogue store of a (v0, v1) pair at logical (t, c)
// =====================================================================
template<int MODE, int ISK>
__device__ __forceinline__ void store_pair(int t, int c, float v0, float v1,
                                           const float* __restrict__ bias,
                                           float* __restrict__ outp)
{
    if (MODE == 0) {
        int seg = c / DD; int oc = c - seg * DD;
        int h = oc >> 6, d0 = oc & 63;
        __nv_bfloat16 *oph, *opl;
        if (seg == 0)      { oph = g_qhi; opl = g_qlo; }
        else if (seg == 1) { oph = g_khi; opl = g_klo; }
        else               { oph = g_vhi; opl = g_vlo; }
        int bT = t >> 11, n = t & 2047;
        size_t base = (((size_t)(bT * HH + h)) * NN + n) * DH + d0;
        store_split2(oph, opl, base, v0 + g_bqkv[c], v1 + g_bqkv[c + 1]);
    } else if (MODE == 1) {
        *(float2*)(outp + (size_t)t * DD + c) =
            make_float2(v0 + bias[c], v1 + bias[c + 1]);
    } else {
        const float dnv = 0.35355339059327373f;   // 64^-0.25
        float* dst = ISK ? g_kp : g_qp;
        *(float2*)(dst + (size_t)t * MF + c) = make_float2(v0 * dnv, v1 * dnv);
    }
}

// =====================================================================
// split-fp32 HMMA GEMM (unchanged from passing R14 kernel)
// =====================================================================
template<int MODE, int ISK, int KD>
__global__ __launch_bounds__(256) void mma_gemm(const float* __restrict__ bias,
                                                float* __restrict__ outp)
{
    __shared__ __nv_bfloat16 shA[2 * 128 * 40];
    __shared__ __nv_bfloat16 shB[2 * 128 * 40];

    const int tid  = threadIdx.x;
    const int lane = tid & 31;
    const int wid  = tid >> 5;
    const int wm   = wid & 3;
    const int wn   = wid >> 2;
    const int row0 = blockIdx.y * 128;
    const int col0 = blockIdx.x * 128;

    const __nv_bfloat16 *Ahi, *Alo, *Bhi, *Blo;
    if (MODE == 0)      { Ahi = g_xhi; Alo = g_xlo; Bhi = g_wqkv_hi; Blo = g_wqkv_lo; }
    else if (MODE == 1) { Ahi = g_ahi; Alo = g_alo; Bhi = g_wo_hi;   Blo = g_wo_lo;   }
    else                { Ahi = ISK ? g_khi : g_qhi; Alo = ISK ? g_klo : g_qlo;
                          Bhi = g_proj_hi; Blo = g_proj_lo; }

    const uint32_t smA = smem_u32(shA);
    const uint32_t smB = smem_u32(shB);

    const int rowL  = tid >> 1;
    const int halfE = (tid & 1) * 16;

    const int numT = 3 * KD / 32;

#define LOAD_TILE(I, BUF) do {                                                   \
        int kcat = (I) * 32; int seg = kcat / KD; int koff = kcat - seg * KD;    \
        const __nv_bfloat16* Ap = (seg == 1) ? Alo : Ahi;                        \
        const __nv_bfloat16* Bp = (seg == 2) ? Blo : Bhi;                        \
        const __nv_bfloat16* ag = Ap + (size_t)(row0 + rowL) * KD + koff + halfE; \
        const __nv_bfloat16* bg = Bp + (size_t)(col0 + rowL) * KD + koff + halfE; \
        uint32_t sa  = smA + ((BUF) * 128 * 40 + rowL * 40 + halfE) * 2;         \
        uint32_t sbv = smB + ((BUF) * 128 * 40 + rowL * 40 + halfE) * 2;         \
        CP_ASYNC16(sa,       ag);                                                \
        CP_ASYNC16(sa  + 16, ag + 8);                                            \
        CP_ASYNC16(sbv,      bg);                                                \
        CP_ASYNC16(sbv + 16, bg + 8);                                            \
    } while (0)

    float c[2][8][4];
#pragma unroll
    for (int mf = 0; mf < 2; mf++)
#pragma unroll
        for (int nf = 0; nf < 8; nf++)
#pragma unroll
            for (int j = 0; j < 4; j++) c[mf][nf][j] = 0.f;

    LOAD_TILE(0, 0);
    CP_COMMIT();

    const int lrow = lane & 15;
    const int lcol = (lane >> 4) << 3;

    for (int i = 0; i < numT; i++) {
        if (i + 1 < numT) {
            LOAD_TILE(i + 1, (i + 1) & 1);
            CP_COMMIT();
            asm volatile("cp.async.wait_group 1;" ::: "memory");
        } else {
            asm volatile("cp.async.wait_group 0;" ::: "memory");
        }
        __syncthreads();

        const int buf = i & 1;
        const uint32_t baseA = smA + buf * (128 * 40 * 2);
        const uint32_t baseB = smB + buf * (128 * 40 * 2);

#pragma unroll
        for (int k16 = 0; k16 < 32; k16 += 16) {
            uint32_t a[2][4], bq[4][4];
#pragma unroll
            for (int mf = 0; mf < 2; mf++) {
                uint32_t ad = baseA + ((wm * 32 + mf * 16 + lrow) * 40 + k16 + lcol) * 2;
                LDSM4(a[mf], ad);
            }
#pragma unroll
            for (int nf4 = 0; nf4 < 4; nf4++) {
                uint32_t bd = baseB + ((wn * 64 + nf4 * 16 + lrow) * 40 + k16 + lcol) * 2;
                LDSM4(bq[nf4], bd);
            }
#pragma unroll
            for (int mf = 0; mf < 2; mf++)
#pragma unroll
                for (int nf4 = 0; nf4 < 4; nf4++) {
                    MMA16816(c[mf][nf4 * 2],     a[mf], bq[nf4][0], bq[nf4][2]);
                    MMA16816(c[mf][nf4 * 2 + 1], a[mf], bq[nf4][1], bq[nf4][3]);
                }
        }
        __syncthreads();
    }
#undef LOAD_TILE

    const int rowA = lane >> 2;
    const int colp = (lane & 3) * 2;
#pragma unroll
    for (int mf = 0; mf < 2; mf++)
#pragma unroll
        for (int nf = 0; nf < 8; nf++) {
            int m = row0 + wm * 32 + mf * 16 + rowA;
            int n = col0 + wn * 64 + nf * 8 + colp;
            store_pair<MODE, ISK>(m,     n, c[mf][nf][0], c[mf][nf][1], bias, outp);
            store_pair<MODE, ISK>(m + 8, n, c[mf][nf][2], c[mf][nf][3], bias, outp);
        }
}

// =====================================================================
// ctx HMMA (unchanged from R14)
// =====================================================================
__global__ __launch_bounds__(256) void ctx_mma()
{
    __shared__ __nv_bfloat16 shA[2 * 32 * 136];
    __shared__ __nv_bfloat16 shV[2 * 32 * 72];

    const int tid = threadIdx.x, lane = tid & 31, wid = tid >> 5;
    const int wm = wid & 3, wn = wid >> 2;
    const int bh = blockIdx.y;
    const int m0 = blockIdx.x * 128;

    const __nv_bfloat16* kph = g_kp_h + (size_t)bh * NN * MF;
    const __nv_bfloat16* kpl = g_kp_l + (size_t)bh * NN * MF;
    const __nv_bfloat16* vhp = g_vhi + (size_t)bh * NN * DH;
    const __nv_bfloat16* vlp = g_vlo + (size_t)bh * NN * DH;

    const uint32_t smA = smem_u32(shA);
    const uint32_t smV = smem_u32(shV);

    const int arow = tid >> 3, achk = tid & 7;
    const int numT = 3 * NN / 32;

#define CTX_LOAD(I, BUF) do {                                                    \
        int kc = (I) * 32; int seg = kc / NN; int noff = kc - seg * NN;          \
        const __nv_bfloat16* Ap = (seg == 1) ? kpl : kph;                        \
        const __nv_bfloat16* Vp = (seg == 2) ? vlp : vhp;                        \
        const __nv_bfloat16* ag = Ap + (size_t)(noff + arow) * MF + m0 + achk * 8; \
        uint32_t sa = smA + ((BUF) * 32 * 136 + arow * 136 + achk * 8) * 2;      \
        CP_ASYNC16(sa,       ag);                                                \
        CP_ASYNC16(sa + 128, ag + 64);                                           \
        const __nv_bfloat16* vg = Vp + (size_t)(noff + arow) * DH + achk * 8;    \
        uint32_t sv = smV + ((BUF) * 32 * 72 + arow * 72 + achk * 8) * 2;        \
        CP_ASYNC16(sv, vg);                                                      \
    } while (0)

    float c[2][4][4];
#pragma unroll
    for (int mf = 0; mf < 2; mf++)
#pragma unroll
        for (int nf = 0; nf < 4; nf++)
#pragma unroll
            for (int j = 0; j < 4; j++) c[mf][nf][j] = 0.f;

    CTX_LOAD(0, 0);
    CP_COMMIT();

    const int trow = lane & 7;
    const int tm8  = ((lane >> 3) & 1) * 8;
    const int tk8  = ((lane >> 4) & 1) * 8;

    for (int i = 0; i < numT; i++) {
        if (i + 1 < numT) {
            CTX_LOAD(i + 1, (i + 1) & 1);
            CP_COMMIT();
            asm volatile("cp.async.wait_group 1;" ::: "memory");
        } else {
            asm volatile("cp.async.wait_group 0;" ::: "memory");
        }
        __syncthreads();

        const int buf = i & 1;
        const uint32_t baseA = smA + buf * (32 * 136 * 2);
        const uint32_t baseV = smV + buf * (32 * 72 * 2);

#pragma unroll
        for (int k16 = 0; k16 < 32; k16 += 16) {
            uint32_t a[2][4], bq[2][4];
#pragma unroll
            for (int mf = 0; mf < 2; mf++) {
                uint32_t ad = baseA + ((k16 + trow + tk8) * 136 + wm * 32 + mf * 16 + tm8) * 2;
                LDSM4T(a[mf], ad);
            }
#pragma unroll
            for (int nf = 0; nf < 2; nf++) {
                uint32_t bd = baseV + ((k16 + trow + tk8) * 72 + wn * 32 + nf * 16 + tm8) * 2;
                LDSM4T(bq[nf], bd);
            }
#pragma unroll
            for (int mf = 0; mf < 2; mf++)
#pragma unroll
                for (int nf = 0; nf < 2; nf++) {
                    MMA16816(c[mf][nf * 2],     a[mf], bq[nf][0], bq[nf][2]);
                    MMA16816(c[mf][nf * 2 + 1], a[mf], bq[nf][1], bq[nf][3]);
                }
        }
        __syncthreads();
    }
#undef CTX_LOAD

    const int rowA = lane >> 2, colp = (lane & 3) * 2;
#pragma unroll
    for (int mf = 0; mf < 2; mf++)
#pragma unroll
        for (int blk = 0; blk < 4; blk++) {
            int m = m0 + wm * 32 + mf * 16 + rowA;
            int d = wn * 32 + blk * 8 + colp;
            size_t b0 = ((size_t)bh * MF + m) * DH + d;
            store_split2(g_ctx_h, g_ctx_l, b0,            c[mf][blk][0], c[mf][blk][1]);
            store_split2(g_ctx_h, g_ctx_l, b0 + 8 * DH,   c[mf][blk][2], c[mf][blk][3]);
        }
}

// =====================================================================
// outattn HMMA (unchanged from R14)
// =====================================================================
__global__ __launch_bounds__(256) void outattn_mma()
{
    __shared__ __nv_bfloat16 shA[2 * 128 * 40];
    __shared__ __nv_bfloat16 shB[2 * 32 * 72];

    const int tid = threadIdx.x, lane = tid & 31, wid = tid >> 5;
    const int wm = wid & 3, wn = wid >> 2;
    const int r0 = blockIdx.x * 128;
    const int bh = r0 >> 11;

    const __nv_bfloat16* cth = g_ctx_h + (size_t)bh * MF * DH;
    const __nv_bfloat16* ctl = g_ctx_l + (size_t)bh * MF * DH;

    const uint32_t smA = smem_u32(shA);
    const uint32_t smB = smem_u32(shB);

    const int rowL = tid >> 1, halfE = (tid & 1) * 16;
    const int brow = tid >> 3, bchk = tid & 7;
    const int numT = 3 * MF / 32;

#define OA_LOAD(I, BUF) do {                                                     \
        int kc = (I) * 32; int seg = kc / MF; int moff = kc - seg * MF;          \
        const __nv_bfloat16* Ap = (seg == 1) ? g_qp_l : g_qp_h;                  \
        const __nv_bfloat16* Bp = (seg == 2) ? ctl : cth;                        \
        const __nv_bfloat16* ag = Ap + (size_t)(r0 + rowL) * MF + moff + halfE;  \
        uint32_t sa = smA + ((BUF) * 128 * 40 + rowL * 40 + halfE) * 2;          \
        CP_ASYNC16(sa,      ag);                                                 \
        CP_ASYNC16(sa + 16, ag + 8);                                             \
        const __nv_bfloat16* bg = Bp + (size_t)(moff + brow) * DH + bchk * 8;    \
        uint32_t sb = smB + ((BUF) * 32 * 72 + brow * 72 + bchk * 8) * 2;        \
        CP_ASYNC16(sb, bg);                                                      \
    } while (0)

    float c[2][4][4];
#pragma unroll
    for (int mf = 0; mf < 2; mf++)
#pragma unroll
        for (int nf = 0; nf < 4; nf++)
#pragma unroll
            for (int j = 0; j < 4; j++) c[mf][nf][j] = 0.f;

    OA_LOAD(0, 0);
    CP_COMMIT();

    const int lrow = lane & 15;
    const int lcol = (lane >> 4) << 3;
    const int trow = lane & 7;
    const int tm8  = ((lane >> 3) & 1) * 8;
    const int tk8  = ((lane >> 4) & 1) * 8;

    for (int i = 0; i < numT; i++) {
        if (i + 1 < numT) {
            OA_LOAD(i + 1, (i + 1) & 1);
            CP_COMMIT();
            asm volatile("cp.async.wait_group 1;" ::: "memory");
        } else {
            asm volatile("cp.async.wait_group 0;" ::: "memory");
        }
        __syncthreads();

        const int buf = i & 1;
        const uint32_t baseA = smA + buf * (128 * 40 * 2);
        const uint32_t baseB = smB + buf * (32 * 72 * 2);

#pragma unroll
        for (int k16 = 0; k16 < 32; k16 += 16) {
            uint32_t a[2][4], bq[2][4];
#pragma unroll
            for (int mf = 0; mf < 2; mf++) {
                uint32_t ad = baseA + ((wm * 32 + mf * 16 + lrow) * 40 + k16 + lcol) * 2;
                LDSM4(a[mf], ad);
            }
#pragma unroll
            for (int nf = 0; nf < 2; nf++) {
                uint32_t bd = baseB + ((k16 + trow + tk8) * 72 + wn * 32 + nf * 16 + tm8) * 2;
                LDSM4T(bq[nf], bd);
            }
#pragma unroll
            for (int mf = 0; mf < 2; mf++)
#pragma unroll
                for (int nf = 0; nf < 2; nf++) {
                    MMA16816(c[mf][nf * 2],     a[mf], bq[nf][0], bq[nf][2]);
                    MMA16816(c[mf][nf * 2 + 1], a[mf], bq[nf][1], bq[nf][3]);
                }
        }
        __syncthreads();
    }
#undef OA_LOAD

    const int rowA = lane >> 2, colp = (lane & 3) * 2;
    const int b = bh / HH, h = bh - b * HH;
#pragma unroll
    for (int mf = 0; mf < 2; mf++)
#pragma unroll
        for (int blk = 0; blk < 4; blk++) {
            int r = r0 + wm * 32 + mf * 16 + rowA;
            int d = wn * 32 + blk * 8 + colp;
            {
                float di = g_dinv[r];
                int t = b * NN + (r & 2047);
                store_split2(g_ahi, g_alo, (size_t)t * DD + h * DH + d,
                             c[mf][blk][0] * di, c[mf][blk][1] * di);
            }
            {
                int r2 = r + 8;
                float di = g_dinv[r2];
                int t = b * NN + (r2 & 2047);
                store_split2(g_ahi, g_alo, (size_t)t * DD + h * DH + d,
                             c[mf][blk][2] * di, c[mf][blk][3] * di);
            }
        }
}

// =====================================================================
// split helpers: fp32 -> (hi, lo) bf16
// =====================================================================
__device__ __forceinline__ void split_vec(float4 v, __nv_bfloat162* h2,
                                          __nv_bfloat162* l2, size_t i4)
{
    __nv_bfloat16 a = __float2bfloat16(v.x), b = __float2bfloat16(v.y);
    __nv_bfloat16 c = __float2bfloat16(v.z), d = __float2bfloat16(v.w);
    __nv_bfloat162 H0, H1, L0, L1;
    H0.x = a; H0.y = b; H1.x = c; H1.y = d;
    L0.x = __float2bfloat16(v.x - __bfloat162float(a));
    L0.y = __float2bfloat16(v.y - __bfloat162float(b));
    L1.x = __float2bfloat16(v.z - __bfloat162float(c));
    L1.y = __float2bfloat16(v.w - __bfloat162float(d));
    h2[2 * i4] = H0; h2[2 * i4 + 1] = H1;
    l2[2 * i4] = L0; l2[2 * i4 + 1] = L1;
}

__global__ void split_x_kernel(const float* __restrict__ x) {
    size_t i = (size_t)blockIdx.x * 256 + threadIdx.x;
    split_vec(((const float4*)x)[i], (__nv_bfloat162*)g_xhi, (__nv_bfloat162*)g_xlo, i);
}
__global__ void split_wqkv_kernel(const float* __restrict__ Wq,
                                  const float* __restrict__ Wk,
                                  const float* __restrict__ Wv) {
    int z = blockIdx.y;
    const float* W = (z == 0) ? Wq : (z == 1) ? Wk : Wv;
    size_t i = (size_t)blockIdx.x * 256 + threadIdx.x;
    __nv_bfloat162* h = (__nv_bfloat162*)(g_wqkv_hi + (size_t)z * DD * DD);
    __nv_bfloat162* l = (__nv_bfloat162*)(g_wqkv_lo + (size_t)z * DD * DD);
    split_vec(((const float4*)W)[i], h, l, i);
}
__global__ void split_wo_kernel(const float* __restrict__ Wo) {
    size_t i = (size_t)blockIdx.x * 256 + threadIdx.x;
    split_vec(((const float4*)Wo)[i], (__nv_bfloat162*)g_wo_hi, (__nv_bfloat162*)g_wo_lo, i);
}
__global__ void split_proj_kernel(const float* __restrict__ p) {
    size_t i = (size_t)blockIdx.x * 256 + threadIdx.x;
    split_vec(((const float4*)p)[i], (__nv_bfloat162*)g_proj_hi, (__nv_bfloat162*)g_proj_lo, i);
}
__global__ void bias_cat_kernel(const float* __restrict__ bq,
                                const float* __restrict__ bk,
                                const float* __restrict__ bv) {
    int z = blockIdx.x;
    const float* b = (z == 0) ? bq : (z == 1) ? bk : bv;
    g_bqkv[z * DD + threadIdx.x] = b[threadIdx.x];
}

// =====================================================================
// small kernels
// =====================================================================
__global__ void diag_kernel()
{
    int z = blockIdx.y;
    const __nv_bfloat16* ph = (z ? g_khi : g_qhi);
    const __nv_bfloat16* pl = (z ? g_klo : g_qlo);
    int warp = threadIdx.x >> 5, lane = threadIdx.x & 31;
    int r = blockIdx.x * 8 + warp;
    size_t base = (size_t)r * DH;
    float a = __bfloat162float(ph[base + lane])      + __bfloat162float(pl[base + lane]);
    float b = __bfloat162float(ph[base + lane + 32]) + __bfloat162float(pl[base + lane + 32]);
    float s = a * a + b * b;
#pragma unroll
    for (int o = 16; o; o >>= 1) s += __shfl_xor_sync(0xffffffffu, s, o);
    if (lane == 0) g_diag[z * RR + r] = s * 0.0625f;
}

// k-only per-row max of raw xp
__global__ void rowmax_kernel()
{
    int warp = threadIdx.x >> 5, lane = threadIdx.x & 31;
    int r = blockIdx.x * 8 + warp;
    const float* p = g_kp + (size_t)r * MF;
    float mx = -1e30f;
#pragma unroll
    for (int i = 0; i < 8; i++) mx = fmaxf(mx, p[lane + i * 32]);
#pragma unroll
    for (int o = 16; o; o >>= 1) mx = fmaxf(mx, __shfl_xor_sync(0xffffffffu, mx, o));
    if (lane == 0) g_rmax[r] = mx;
}

__global__ void kheadmax_kernel()
{
    int bh = blockIdx.x, tid = threadIdx.x;
    const float* p = g_rmax + (size_t)bh * NN;
    float mx = -1e30f;
    for (int i = tid; i < NN; i += 256) mx = fmaxf(mx, p[i]);
    __shared__ float sm[256];
    sm[tid] = mx;
    __syncthreads();
    for (int s = 128; s > 0; s >>= 1) {
        if (tid < s) sm[tid] = fmaxf(sm[tid], sm[tid + s]);
        __syncthreads();
    }
    if (tid == 0) g_kmax[bh] = sm[0];
    g_ksum[bh * MF + tid] = 0.f;
}

// k path: phi = ratio*(exp(xp - diag - headmax) + eps), column-parallel,
// poly exp, register ksum accumulation. grid (NN/256, NBH)
__global__ void kexp_kernel()
{
    int bh  = blockIdx.y;
    int m   = threadIdx.x;
    int r0  = bh * NN + blockIdx.x * 256;
    float headsub = g_kmax[bh];
    const float* diag = g_diag + RR;
    float acc = 0.f;
    for (int i = 0; i < 256; i++) {
        int r = r0 + i;
        size_t idx = (size_t)r * MF + m;
        float ph = 0.0625f * (fexp(g_kp[idx] - diag[r] - headsub) + 1e-4f);
        __nv_bfloat16 hh = __float2bfloat16(ph);
        g_kp_h[idx] = hh;
        g_kp_l[idx] = __float2bfloat16(ph - __bfloat162float(hh));
        acc += ph;
    }
    atomicAdd(&g_ksum[bh * MF + m], acc);
}

// q path: fused rowmax + exp + split store. Warp per row; each lane holds
// 8 consecutive xp values; shfl max; poly exp; 16B hi + 16B lo stores.
struct B8 { __nv_bfloat162 v[4]; };

__global__ void qexp_kernel()
{
    int warp = threadIdx.x >> 5, lane = threadIdx.x & 31;
    int r = blockIdx.x * 8 + warp;
    const float* p = g_qp + (size_t)r * MF;
    float v[8];
    *(float4*)(v)     = *(const float4*)(p + lane * 8);
    *(float4*)(v + 4) = *(const float4*)(p + lane * 8 + 4);
    float mx = v[0];
#pragma unroll
    for (int i = 1; i < 8; i++) mx = fmaxf(mx, v[i]);
#pragma unroll
    for (int o = 16; o; o >>= 1) mx = fmaxf(mx, __shfl_xor_sync(0xffffffffu, mx, o));
    float sub = g_diag[r] + mx;

    B8 H, L;
#pragma unroll
    for (int i = 0; i < 4; i++) {
        float p0 = 0.0625f * (fexp(v[2 * i]     - sub) + 1e-4f);
        float p1 = 0.0625f * (fexp(v[2 * i + 1] - sub) + 1e-4f);
        __nv_bfloat16 h0 = __float2bfloat16(p0), h1 = __float2bfloat16(p1);
        H.v[i].x = h0; H.v[i].y = h1;
        L.v[i].x = __float2bfloat16(p0 - __bfloat162float(h0));
        L.v[i].y = __float2bfloat16(p1 - __bfloat162float(h1));
    }
    size_t base = (size_t)r * MF + lane * 8;
    *(B8*)(g_qp_h + base) = H;
    *(B8*)(g_qp_l + base) = L;
}

__global__ void dden_kernel()
{
    int warp = threadIdx.x >> 5, lane = threadIdx.x & 31;
    int r  = blockIdx.x * 8 + warp;
    int bh = r >> 11;
    const __nv_bfloat16* qh = g_qp_h + (size_t)r * MF;
    const __nv_bfloat16* ql = g_qp_l + (size_t)r * MF;
    const float* ks = g_ksum + bh * MF;
    float s = 0.f;
#pragma unroll
    for (int i = 0; i < 8; i++) {
        int j = lane + i * 32;
        float qv = __bfloat162float(qh[j]) + __bfloat162float(ql[j]);
        s += qv * ks[j];
    }
#pragma unroll
    for (int o = 16; o; o >>= 1) s += __shfl_xor_sync(0xffffffffu, s, o);
    if (lane == 0) g_dinv[r] = 1.f / s;
}

// =====================================================================
extern "C" void kernel_launch(void* const* d_in, const int* in_sizes, int n_in,
                              void* d_out, int out_size)
{
    const float* x    = (const float*)d_in[0];
    const float* Wq   = (const float*)d_in[1];
    const float* bq   = (const float*)d_in[2];
    const float* Wk   = (const float*)d_in[3];
    const float* bk   = (const float*)d_in[4];
    const float* Wv   = (const float*)d_in[5];
    const float* bv   = (const float*)d_in[6];
    const float* Wo   = (const float*)d_in[7];
    const float* bo   = (const float*)d_in[8];
    const float* proj = (const float*)d_in[9];
    float* out = (float*)d_out;

    // input splits
    split_wqkv_kernel<<<dim3(DD * DD / 1024, 3), 256>>>(Wq, Wk, Wv);
    split_wo_kernel<<<DD * DD / 1024, 256>>>(Wo);
    split_proj_kernel<<<MF * DH / 1024, 256>>>(proj);
    bias_cat_kernel<<<3, DD>>>(bq, bk, bv);
    split_x_kernel<<<TT * DD / 1024, 256>>>(x);

    // QKV projection -> q/k/v hi/lo bf16 head layout
    mma_gemm<0, 0, 768><<<dim3(3 * DD / 128, TT / 128), 256>>>(nullptr, nullptr);

    diag_kernel<<<dim3(RR / 8, 2), 256>>>();

    // feature projections -> raw xp fp32 in g_qp / g_kp
    mma_gemm<2, 0, 64><<<dim3(MF / 128, RR / 128), 256>>>(nullptr, nullptr);
    mma_gemm<2, 1, 64><<<dim3(MF / 128, RR / 128), 256>>>(nullptr, nullptr);

    // k: rowmax -> headmax -> poly exp (+ksum); q: fused rowmax+exp
    rowmax_kernel<<<RR / 8, 256>>>();
    kheadmax_kernel<<<NBH, 256>>>();
    kexp_kernel<<<dim3(NN / 256, NBH), 256>>>();
    qexp_kernel<<<RR / 8, 256>>>();

    // ctx = kp^T @ v  (HMMA, trans loads) -> ctx hi/lo
    ctx_mma<<<dim3(2, NBH), 256>>>();

    dden_kernel<<<RR / 8, 256>>>();

    // out_attn = (qp @ ctx) * dinv (HMMA) -> attn hi/lo token layout
    outattn_mma<<<RR / 128, 256>>>();

    // output projection
    mma_gemm<1, 0, 768><<<dim3(DD / 128, TT / 128), 256>>>(bo, out);
}